// round 3
// baseline (speedup 1.0000x reference)
#include <cuda_runtime.h>
#include <cuda_bf16.h>

#define BB 8
#define SS 2048
#define DE 512
#define HH 8
#define DH 64

// Scratch (allocation-free: device globals)
__device__ float g_q[BB*HH*SS*DH];      // [b][h][s][d], pre-scaled by 1/sqrt(64)
__device__ float g_k[BB*HH*SS*DH];      // [b][h][s][d]
__device__ float g_v[BB*HH*SS*DH];      // [b][h][s][d]
__device__ float g_att[BB*SS*DE];       // [b][s][h*64+d]
__device__ unsigned char g_mask[BB*SS];

// ---------------------------------------------------------------------------
// Mask dtype probe + normalize: bool may arrive as u8 / int32 / float32.
// ---------------------------------------------------------------------------
__global__ void mask_norm_kernel(const void* __restrict__ mraw)
{
    __shared__ int s_nz, s_3f;
    const int tid = threadIdx.x;
    if (tid == 0) { s_nz = 0; s_3f = 0; }
    __syncthreads();
    const unsigned char* u8 = (const unsigned char*)mraw;
    int nz = 0, c3 = 0;
    for (int i = tid; i < BB*SS; i += 256) {
        unsigned char c = u8[i];
        nz += (c != 0);
        c3 += (c == 0x3F);
    }
    atomicAdd(&s_nz, nz);
    atomicAdd(&s_3f, c3);
    __syncthreads();
    // float32: ~410 bytes equal to 0x3F in first 16KB. int32: ~410 nonzero
    // bytes, no 0x3F. uint8: ~1638 nonzero bytes.
    int mode = (s_3f > 100) ? 2 : ((s_nz > 1000) ? 0 : 1);
    for (int i = tid; i < BB*SS; i += 256) {
        unsigned char m;
        if (mode == 2)      m = (((const float*)mraw)[i] != 0.0f);
        else if (mode == 1) m = (((const int*)mraw)[i] != 0);
        else                m = (u8[i] != 0);
        g_mask[i] = m;
    }
}

// ---------------------------------------------------------------------------
// QKV projection: q = 0.125 * x_p @ Wq ; [k|v] = x_pcre @ Wkv
// 128x128x8 SGEMM tiles, 256 threads, 8x8 micro (2x2 slabs of 4).
// grid.x: 12 N-tiles (0-3 q, 4-7 k, 8-11 v), grid.y: 128 M-tiles
// ---------------------------------------------------------------------------
__global__ __launch_bounds__(256, 2) void proj_kernel(
    const float* __restrict__ xp, const float* __restrict__ xpcre,
    const float* __restrict__ Wq, const float* __restrict__ Wkv)
{
    const int nt = blockIdx.x;
    const int mt = blockIdx.y;
    const int grp = nt >> 2;
    const int ncol0 = (nt & 3) * 128;
    const float* __restrict__ A = (grp == 0) ? xp : xpcre;
    const float* __restrict__ W = (grp == 0) ? Wq : Wkv;
    const int ldw = (grp == 0) ? 512 : 1024;
    const int wc0 = (grp == 2) ? (512 + ncol0) : ncol0;
    float* dst = (grp == 0) ? g_q : ((grp == 1) ? g_k : g_v);
    const float osc = (grp == 0) ? 0.125f : 1.0f;

    __shared__ __align__(16) float As[8][132];
    __shared__ __align__(16) float Bs[8][128];

    const int tid = threadIdx.x;
    const int tx = tid & 15;
    const int ty = tid >> 4;
    const int m0 = mt * 128;

    const int a_row = tid >> 1;
    const int a_k   = (tid & 1) * 4;
    const int b_k   = tid >> 5;
    const int b_n   = (tid & 31) * 4;

    float c[8][8];
#pragma unroll
    for (int i = 0; i < 8; i++)
#pragma unroll
        for (int j = 0; j < 8; j++) c[i][j] = 0.f;

    for (int k0 = 0; k0 < 512; k0 += 8) {
        float4 av = *(const float4*)(A + (size_t)(m0 + a_row) * 512 + (k0 + a_k));
        As[a_k + 0][a_row] = av.x;
        As[a_k + 1][a_row] = av.y;
        As[a_k + 2][a_row] = av.z;
        As[a_k + 3][a_row] = av.w;
        *(float4*)(&Bs[b_k][b_n]) =
            *(const float4*)(W + (size_t)(k0 + b_k) * ldw + (wc0 + b_n));
        __syncthreads();
#pragma unroll
        for (int kk = 0; kk < 8; kk++) {
            float4 a0 = *(const float4*)(&As[kk][ty * 4]);
            float4 a1 = *(const float4*)(&As[kk][64 + ty * 4]);
            float4 b0 = *(const float4*)(&Bs[kk][tx * 4]);
            float4 b1 = *(const float4*)(&Bs[kk][64 + tx * 4]);
            float am[8] = {a0.x, a0.y, a0.z, a0.w, a1.x, a1.y, a1.z, a1.w};
            float bn[8] = {b0.x, b0.y, b0.z, b0.w, b1.x, b1.y, b1.z, b1.w};
#pragma unroll
            for (int i = 0; i < 8; i++)
#pragma unroll
                for (int j = 0; j < 8; j++) c[i][j] += am[i] * bn[j];
        }
        __syncthreads();
    }
#pragma unroll
    for (int i = 0; i < 8; i++) {
        int r  = m0 + (i >> 2) * 64 + ty * 4 + (i & 3);
        int bb = r >> 11;
        int s  = r & 2047;
#pragma unroll
        for (int js = 0; js < 2; js++) {
            int col = ncol0 + js * 64 + tx * 4;
            int h = col >> 6;
            int d = col & 63;
            float4 v;
            v.x = c[i][js * 4 + 0] * osc;
            v.y = c[i][js * 4 + 1] * osc;
            v.z = c[i][js * 4 + 2] * osc;
            v.w = c[i][js * 4 + 3] * osc;
            *(float4*)(dst + ((size_t)(bb * 8 + h) * 2048 + s) * 64 + d) = v;
        }
    }
}

// ---------------------------------------------------------------------------
// Flash attention: one CTA per (qtile=64 rows, h, b). 256 threads (16x16),
// 4x4 micro-tiles. Online softmax with bias+mask. smem: Qs^T, Ks^T/Ps union, Vs.
// ---------------------------------------------------------------------------
__global__ __launch_bounds__(256, 2) void attn_kernel(
    const float* __restrict__ bias, const float* __restrict__ gamma_f)
{
    extern __shared__ __align__(16) float sm[];
    float* Qs = sm;               // [d][m]  (64*64)
    float* KP = sm + 4096;        // Ks: [d][n] (64*64) / Ps: [n*68+m] (64*68)
    float* Vs = sm + 4096 + 4352; // [n][d]  (64*64)

    const int qt = blockIdx.x, h = blockIdx.y, b = blockIdx.z;
    const int tid = threadIdx.x;
    const int tx = tid & 15, ty = tid >> 4;
    const float gamma = gamma_f[h];

    const float* qp = g_q + ((size_t)(b * 8 + h) * 2048 + qt * 64) * 64;
    const float* kp = g_k + (size_t)(b * 8 + h) * 2048 * 64;
    const float* vp = g_v + (size_t)(b * 8 + h) * 2048 * 64;
    const unsigned char* mkb = g_mask + b * 2048;

    // Load Q transposed into smem (lanes cover consecutive m -> STS conflict-free)
    {
        const int m = tid & 63;
        const int dbase = (tid >> 6) * 4;
#pragma unroll
        for (int r = 0; r < 4; r++) {
            int d = dbase + r * 16;
            float4 v = *(const float4*)(qp + m * 64 + d);
            Qs[(d + 0) * 64 + m] = v.x;
            Qs[(d + 1) * 64 + m] = v.y;
            Qs[(d + 2) * 64 + m] = v.z;
            Qs[(d + 3) * 64 + m] = v.w;
        }
    }

    float o[16];
#pragma unroll
    for (int i = 0; i < 16; i++) o[i] = 0.f;
    float mrun[4] = {-1e30f, -1e30f, -1e30f, -1e30f};
    float lrun[4] = {0.f, 0.f, 0.f, 0.f};

    for (int kt = 0; kt < 32; kt++) {
        __syncthreads();   // KP/Vs free to overwrite
        {
            const int n = tid & 63;
            const int dbase = (tid >> 6) * 4;
            const float* kq = kp + (size_t)(kt * 64) * 64;
#pragma unroll
            for (int r = 0; r < 4; r++) {
                int d = dbase + r * 16;
                float4 v = *(const float4*)(kq + n * 64 + d);
                KP[(d + 0) * 64 + n] = v.x;
                KP[(d + 1) * 64 + n] = v.y;
                KP[(d + 2) * 64 + n] = v.z;
                KP[(d + 3) * 64 + n] = v.w;
            }
#pragma unroll
            for (int r = 0; r < 4; r++) {
                int e = tid + r * 256;
                int n2 = e >> 4, d4 = (e & 15) * 4;
                *(float4*)(Vs + n2 * 64 + d4) =
                    *(const float4*)(vp + (size_t)(kt * 64 + n2) * 64 + d4);
            }
        }
        // Prefetch bias + mask for this tile (consumed after the matmul)
        uchar4 mv = *(const uchar4*)(mkb + kt * 64 + tx * 4);
        float4 bvf[4];
#pragma unroll
        for (int mi = 0; mi < 4; mi++)
            bvf[mi] = *(const float4*)(bias +
                        ((size_t)b * 2048 + qt * 64 + ty * 4 + mi) * 2048 +
                        kt * 64 + tx * 4);
        __syncthreads();   // tiles ready

        // S = Q K^T (q pre-scaled by 1/8)
        float sa[16];
#pragma unroll
        for (int i = 0; i < 16; i++) sa[i] = 0.f;
#pragma unroll 8
        for (int d = 0; d < 64; d++) {
            float4 qa = *(const float4*)(Qs + d * 64 + ty * 4);
            float4 kb = *(const float4*)(KP + d * 64 + tx * 4);
            sa[0]  += qa.x * kb.x;  sa[1]  += qa.x * kb.y;
            sa[2]  += qa.x * kb.z;  sa[3]  += qa.x * kb.w;
            sa[4]  += qa.y * kb.x;  sa[5]  += qa.y * kb.y;
            sa[6]  += qa.y * kb.z;  sa[7]  += qa.y * kb.w;
            sa[8]  += qa.z * kb.x;  sa[9]  += qa.z * kb.y;
            sa[10] += qa.z * kb.z;  sa[11] += qa.z * kb.w;
            sa[12] += qa.w * kb.x;  sa[13] += qa.w * kb.y;
            sa[14] += qa.w * kb.z;  sa[15] += qa.w * kb.w;
        }

        // bias + mask + online softmax
        float p[16];
        float sc[4];
#pragma unroll
        for (int mi = 0; mi < 4; mi++) {
            float s0 = mv.x ? -1e9f : sa[mi * 4 + 0] + gamma * bvf[mi].x;
            float s1 = mv.y ? -1e9f : sa[mi * 4 + 1] + gamma * bvf[mi].y;
            float s2 = mv.z ? -1e9f : sa[mi * 4 + 2] + gamma * bvf[mi].z;
            float s3 = mv.w ? -1e9f : sa[mi * 4 + 3] + gamma * bvf[mi].w;
            float tm = fmaxf(fmaxf(s0, s1), fmaxf(s2, s3));
#pragma unroll
            for (int msk = 8; msk; msk >>= 1)
                tm = fmaxf(tm, __shfl_xor_sync(0xffffffffu, tm, msk));
            float mn = fmaxf(mrun[mi], tm);
            float scale = __expf(mrun[mi] - mn);
            mrun[mi] = mn;
            float p0 = __expf(s0 - mn);
            float p1 = __expf(s1 - mn);
            float p2 = __expf(s2 - mn);
            float p3 = __expf(s3 - mn);
            float rs = (p0 + p1) + (p2 + p3);
#pragma unroll
            for (int msk = 8; msk; msk >>= 1)
                rs += __shfl_xor_sync(0xffffffffu, rs, msk);
            lrun[mi] = lrun[mi] * scale + rs;
            sc[mi] = scale;
            p[mi * 4 + 0] = p0; p[mi * 4 + 1] = p1;
            p[mi * 4 + 2] = p2; p[mi * 4 + 3] = p3;
        }
#pragma unroll
        for (int mi = 0; mi < 4; mi++)
#pragma unroll
            for (int di = 0; di < 4; di++) o[mi * 4 + di] *= sc[mi];

        __syncthreads();   // done reading Ks
#pragma unroll
        for (int ni = 0; ni < 4; ni++)
#pragma unroll
            for (int mi = 0; mi < 4; mi++)
                KP[(tx * 4 + ni) * 68 + ty * 4 + mi] = p[mi * 4 + ni];
        __syncthreads();   // Ps ready

        // O += P V
#pragma unroll 8
        for (int n = 0; n < 64; n++) {
            float4 pa = *(const float4*)(KP + n * 68 + ty * 4);
            float4 vb = *(const float4*)(Vs + n * 64 + tx * 4);
            o[0]  += pa.x * vb.x;  o[1]  += pa.x * vb.y;
            o[2]  += pa.x * vb.z;  o[3]  += pa.x * vb.w;
            o[4]  += pa.y * vb.x;  o[5]  += pa.y * vb.y;
            o[6]  += pa.y * vb.z;  o[7]  += pa.y * vb.w;
            o[8]  += pa.z * vb.x;  o[9]  += pa.z * vb.y;
            o[10] += pa.z * vb.z;  o[11] += pa.z * vb.w;
            o[12] += pa.w * vb.x;  o[13] += pa.w * vb.y;
            o[14] += pa.w * vb.z;  o[15] += pa.w * vb.w;
        }
    }

#pragma unroll
    for (int mi = 0; mi < 4; mi++) {
        float inv = 1.0f / lrun[mi];
        float4 v;
        v.x = o[mi * 4 + 0] * inv;
        v.y = o[mi * 4 + 1] * inv;
        v.z = o[mi * 4 + 2] * inv;
        v.w = o[mi * 4 + 3] * inv;
        *(float4*)(g_att + ((size_t)b * 2048 + qt * 64 + ty * 4 + mi) * 512 +
                   h * 64 + tx * 4) = v;
    }
}

// ---------------------------------------------------------------------------
// FF: y = x_p + (att @ Wff + bff)  -> written to d_out (pre-LN)
// ---------------------------------------------------------------------------
__global__ __launch_bounds__(256, 2) void ff_kernel(
    const float* __restrict__ Wff, const float* __restrict__ bff,
    const float* __restrict__ xp, float* __restrict__ out)
{
    const int nt = blockIdx.x;     // 0..3
    const int mt = blockIdx.y;     // 0..127
    const int ncol0 = nt * 128;

    __shared__ __align__(16) float As[8][132];
    __shared__ __align__(16) float Bs[8][128];

    const int tid = threadIdx.x;
    const int tx = tid & 15;
    const int ty = tid >> 4;
    const int m0 = mt * 128;

    const int a_row = tid >> 1;
    const int a_k   = (tid & 1) * 4;
    const int b_k   = tid >> 5;
    const int b_n   = (tid & 31) * 4;

    float c[8][8];
#pragma unroll
    for (int i = 0; i < 8; i++)
#pragma unroll
        for (int j = 0; j < 8; j++) c[i][j] = 0.f;

    for (int k0 = 0; k0 < 512; k0 += 8) {
        float4 av = *(const float4*)(g_att + (size_t)(m0 + a_row) * 512 + (k0 + a_k));
        As[a_k + 0][a_row] = av.x;
        As[a_k + 1][a_row] = av.y;
        As[a_k + 2][a_row] = av.z;
        As[a_k + 3][a_row] = av.w;
        *(float4*)(&Bs[b_k][b_n]) =
            *(const float4*)(Wff + (size_t)(k0 + b_k) * 512 + (ncol0 + b_n));
        __syncthreads();
#pragma unroll
        for (int kk = 0; kk < 8; kk++) {
            float4 a0 = *(const float4*)(&As[kk][ty * 4]);
            float4 a1 = *(const float4*)(&As[kk][64 + ty * 4]);
            float4 b0 = *(const float4*)(&Bs[kk][tx * 4]);
            float4 b1 = *(const float4*)(&Bs[kk][64 + tx * 4]);
            float am[8] = {a0.x, a0.y, a0.z, a0.w, a1.x, a1.y, a1.z, a1.w};
            float bn[8] = {b0.x, b0.y, b0.z, b0.w, b1.x, b1.y, b1.z, b1.w};
#pragma unroll
            for (int i = 0; i < 8; i++)
#pragma unroll
                for (int j = 0; j < 8; j++) c[i][j] += am[i] * bn[j];
        }
        __syncthreads();
    }
#pragma unroll
    for (int i = 0; i < 8; i++) {
        int r = m0 + (i >> 2) * 64 + ty * 4 + (i & 3);
#pragma unroll
        for (int js = 0; js < 2; js++) {
            int col = ncol0 + js * 64 + tx * 4;
            float4 bb = *(const float4*)(bff + col);
            float4 xx = *(const float4*)(xp + (size_t)r * 512 + col);
            float4 v;
            v.x = c[i][js * 4 + 0] + bb.x + xx.x;
            v.y = c[i][js * 4 + 1] + bb.y + xx.y;
            v.z = c[i][js * 4 + 2] + bb.z + xx.z;
            v.w = c[i][js * 4 + 3] + bb.w + xx.w;
            *(float4*)(out + (size_t)r * 512 + col) = v;
        }
    }
}

// ---------------------------------------------------------------------------
// LayerNorm in-place on d_out: one block per row of 512.
// ---------------------------------------------------------------------------
__global__ __launch_bounds__(128) void ln_kernel(
    float* __restrict__ y, const float* __restrict__ g,
    const float* __restrict__ be)
{
    const int row = blockIdx.x;
    const int tid = threadIdx.x;
    float4 v = *(const float4*)(y + (size_t)row * 512 + tid * 4);
    float s = (v.x + v.y) + (v.z + v.w);
    float q = (v.x * v.x + v.y * v.y) + (v.z * v.z + v.w * v.w);
#pragma unroll
    for (int msk = 16; msk; msk >>= 1) {
        s += __shfl_xor_sync(0xffffffffu, s, msk);
        q += __shfl_xor_sync(0xffffffffu, q, msk);
    }
    __shared__ float ss[4], sq[4];
    const int w = tid >> 5;
    if ((tid & 31) == 0) { ss[w] = s; sq[w] = q; }
    __syncthreads();
    s = (ss[0] + ss[1]) + (ss[2] + ss[3]);
    q = (sq[0] + sq[1]) + (sq[2] + sq[3]);
    const float mu = s * (1.0f / 512.0f);
    const float var = q * (1.0f / 512.0f) - mu * mu;
    const float rs = rsqrtf(var + 1e-5f);
    float4 gg = *(const float4*)(g + tid * 4);
    float4 bb = *(const float4*)(be + tid * 4);
    float4 r;
    r.x = (v.x - mu) * rs * gg.x + bb.x;
    r.y = (v.y - mu) * rs * gg.y + bb.y;
    r.z = (v.z - mu) * rs * gg.z + bb.z;
    r.w = (v.w - mu) * rs * gg.w + bb.w;
    *(float4*)(y + (size_t)row * 512 + tid * 4) = r;
}

// ---------------------------------------------------------------------------
extern "C" void kernel_launch(void* const* d_in, const int* in_sizes, int n_in,
                              void* d_out, int out_size)
{
    const float* xp      = (const float*)d_in[0];
    const float* xpcre   = (const float*)d_in[1];
    const float* bias    = (const float*)d_in[2];
    const void*  mask    = d_in[3];
    const float* Wq      = (const float*)d_in[4];
    const float* Wkv     = (const float*)d_in[5];
    const float* Wff     = (const float*)d_in[6];
    const float* bff     = (const float*)d_in[7];
    const float* gamma_f = (const float*)d_in[8];
    const float* ln_g    = (const float*)d_in[9];
    const float* ln_b    = (const float*)d_in[10];
    float* out = (float*)d_out;

    const int attn_smem = (4096 + 64 * 68 + 4096) * 4;  // 50176 B
    cudaFuncSetAttribute(attn_kernel,
                         cudaFuncAttributeMaxDynamicSharedMemorySize, attn_smem);

    mask_norm_kernel<<<1, 256>>>(mask);

    dim3 pg(12, 128);
    proj_kernel<<<pg, 256>>>(xp, xpcre, Wq, Wkv);

    dim3 ag(32, 8, 8);  // (qtile, h, b): heads adjacent -> shared bias stream in L2
    attn_kernel<<<ag, 256, attn_smem>>>(bias, gamma_f);

    dim3 fg(4, 128);
    ff_kernel<<<fg, 256>>>(Wff, bff, xp, out);

    ln_kernel<<<BB * SS, 128>>>(out, ln_g, ln_b);
}

// round 7
// speedup vs baseline: 1.9842x; 1.9842x over previous
#include <cuda_runtime.h>
#include <cuda_bf16.h>
#include <cstdint>

#define BB 8
#define SS 2048
#define DE 512
#define HH 8
#define DH 64

// Scratch (allocation-free: device globals)
__device__ float g_q[BB*HH*SS*DH];      // [b][h][s][d], pre-scaled by 1/8
__device__ float g_k[BB*HH*SS*DH];      // [b][h][s][d]
__device__ float g_v[BB*HH*SS*DH];      // [b][h][s][d]
__device__ float g_att[BB*SS*DE];       // [b][s][h*64+d]
__device__ unsigned char g_mask[BB*SS];
// Fragment-linear (mma B-frag) layouts: [bh][ktile][fraggrp(64)][lane(32)][2]
__device__ __align__(16) float g_ksw[BB*HH*32*4096];
__device__ __align__(16) float g_vsw[BB*HH*32*4096];

// ---------------------------------------------------------------------------
// small helpers
// ---------------------------------------------------------------------------
__device__ __forceinline__ uint32_t f2tf32(float f) {
    uint32_t u;
    asm("cvt.rna.tf32.f32 %0, %1;" : "=r"(u) : "f"(f));
    return u;
}
__device__ __forceinline__ void mma8(float4& c, const uint32_t a[4],
                                     uint32_t b0, uint32_t b1) {
    asm volatile(
        "mma.sync.aligned.m16n8k8.row.col.f32.tf32.tf32.f32 "
        "{%0,%1,%2,%3},{%4,%5,%6,%7},{%8,%9},{%0,%1,%2,%3};"
        : "+f"(c.x), "+f"(c.y), "+f"(c.z), "+f"(c.w)
        : "r"(a[0]), "r"(a[1]), "r"(a[2]), "r"(a[3]), "r"(b0), "r"(b1));
}
__device__ __forceinline__ void cpasync16(float* s, const float* g) {
    uint32_t sa = (uint32_t)__cvta_generic_to_shared(s);
    asm volatile("cp.async.cg.shared.global [%0], [%1], 16;" :: "r"(sa), "l"(g));
}
__device__ __forceinline__ void cp_commit() {
    asm volatile("cp.async.commit_group;" ::: "memory");
}
template <int N>
__device__ __forceinline__ void cp_wait() {
    asm volatile("cp.async.wait_group %0;" :: "n"(N) : "memory");
}

// ---------------------------------------------------------------------------
// Mask dtype probe + normalize: bool may arrive as u8 / int32 / float32.
// ---------------------------------------------------------------------------
__global__ void mask_norm_kernel(const void* __restrict__ mraw)
{
    __shared__ int s_nz, s_3f;
    const int tid = threadIdx.x;
    if (tid == 0) { s_nz = 0; s_3f = 0; }
    __syncthreads();
    const unsigned char* u8 = (const unsigned char*)mraw;
    int nz = 0, c3 = 0;
    for (int i = tid; i < BB*SS; i += 256) {
        unsigned char c = u8[i];
        nz += (c != 0);
        c3 += (c == 0x3F);
    }
    atomicAdd(&s_nz, nz);
    atomicAdd(&s_3f, c3);
    __syncthreads();
    int mode = (s_3f > 100) ? 2 : ((s_nz > 1000) ? 0 : 1);
    for (int i = tid; i < BB*SS; i += 256) {
        unsigned char m;
        if (mode == 2)      m = (((const float*)mraw)[i] != 0.0f);
        else if (mode == 1) m = (((const int*)mraw)[i] != 0);
        else                m = (u8[i] != 0);
        g_mask[i] = m;
    }
}

// ---------------------------------------------------------------------------
// QKV projection (unchanged fp32 SGEMM this round)
// ---------------------------------------------------------------------------
__global__ __launch_bounds__(256, 2) void proj_kernel(
    const float* __restrict__ xp, const float* __restrict__ xpcre,
    const float* __restrict__ Wq, const float* __restrict__ Wkv)
{
    const int nt = blockIdx.x;
    const int mt = blockIdx.y;
    const int grp = nt >> 2;
    const int ncol0 = (nt & 3) * 128;
    const float* __restrict__ A = (grp == 0) ? xp : xpcre;
    const float* __restrict__ W = (grp == 0) ? Wq : Wkv;
    const int ldw = (grp == 0) ? 512 : 1024;
    const int wc0 = (grp == 2) ? (512 + ncol0) : ncol0;
    float* dst = (grp == 0) ? g_q : ((grp == 1) ? g_k : g_v);
    const float osc = (grp == 0) ? 0.125f : 1.0f;

    __shared__ __align__(16) float As[8][132];
    __shared__ __align__(16) float Bs[8][128];

    const int tid = threadIdx.x;
    const int tx = tid & 15;
    const int ty = tid >> 4;
    const int m0 = mt * 128;

    const int a_row = tid >> 1;
    const int a_k   = (tid & 1) * 4;
    const int b_k   = tid >> 5;
    const int b_n   = (tid & 31) * 4;

    float c[8][8];
#pragma unroll
    for (int i = 0; i < 8; i++)
#pragma unroll
        for (int j = 0; j < 8; j++) c[i][j] = 0.f;

    for (int k0 = 0; k0 < 512; k0 += 8) {
        float4 av = *(const float4*)(A + (size_t)(m0 + a_row) * 512 + (k0 + a_k));
        As[a_k + 0][a_row] = av.x;
        As[a_k + 1][a_row] = av.y;
        As[a_k + 2][a_row] = av.z;
        As[a_k + 3][a_row] = av.w;
        *(float4*)(&Bs[b_k][b_n]) =
            *(const float4*)(W + (size_t)(k0 + b_k) * ldw + (wc0 + b_n));
        __syncthreads();
#pragma unroll
        for (int kk = 0; kk < 8; kk++) {
            float4 a0 = *(const float4*)(&As[kk][ty * 4]);
            float4 a1 = *(const float4*)(&As[kk][64 + ty * 4]);
            float4 b0 = *(const float4*)(&Bs[kk][tx * 4]);
            float4 b1 = *(const float4*)(&Bs[kk][64 + tx * 4]);
            float am[8] = {a0.x, a0.y, a0.z, a0.w, a1.x, a1.y, a1.z, a1.w};
            float bn[8] = {b0.x, b0.y, b0.z, b0.w, b1.x, b1.y, b1.z, b1.w};
#pragma unroll
            for (int i = 0; i < 8; i++)
#pragma unroll
                for (int j = 0; j < 8; j++) c[i][j] += am[i] * bn[j];
        }
        __syncthreads();
    }
#pragma unroll
    for (int i = 0; i < 8; i++) {
        int r  = m0 + (i >> 2) * 64 + ty * 4 + (i & 3);
        int bb = r >> 11;
        int s  = r & 2047;
#pragma unroll
        for (int js = 0; js < 2; js++) {
            int col = ncol0 + js * 64 + tx * 4;
            int h = col >> 6;
            int d = col & 63;
            float4 v;
            v.x = c[i][js * 4 + 0] * osc;
            v.y = c[i][js * 4 + 1] * osc;
            v.z = c[i][js * 4 + 2] * osc;
            v.w = c[i][js * 4 + 3] * osc;
            *(float4*)(dst + ((size_t)(bb * 8 + h) * 2048 + s) * 64 + d) = v;
        }
    }
}

// ---------------------------------------------------------------------------
// Repack K and V into mma-B-fragment-linear layout (+ round to tf32).
// K frag (kind 0): fg=(nblk*8+ks): elem j -> K[nblk*8+g][ks*8+tg+4j]
// V frag (kind 1): fg=(dblk*8+ks): elem j -> V[ks*8+tg+4j][dblk*8+g]
// grid: (ktile=32, bh=64, kind=2), 256 threads
// ---------------------------------------------------------------------------
__global__ __launch_bounds__(256) void repack_kv_kernel()
{
    const int kt = blockIdx.x, bh = blockIdx.y, kind = blockIdx.z;
    __shared__ float ts[64][68];
    const float* src = (kind ? g_v : g_k) + ((size_t)bh * 2048 + kt * 64) * 64;
    const int tid = threadIdx.x;
#pragma unroll
    for (int r = 0; r < 4; r++) {
        int e = tid + r * 256;
        int row = e >> 4, c4 = (e & 15) * 4;
        float4 v = *(const float4*)(src + row * 64 + c4);
        ts[row][c4 + 0] = v.x; ts[row][c4 + 1] = v.y;
        ts[row][c4 + 2] = v.z; ts[row][c4 + 3] = v.w;
    }
    __syncthreads();
    const int w = tid >> 5, lane = tid & 31, g = lane >> 2, tg = lane & 3;
    float* dst = (kind ? g_vsw : g_ksw) + ((size_t)bh * 32 + kt) * 4096;
#pragma unroll
    for (int i = 0; i < 8; i++) {
        int fg = w * 8 + i;
        int blk = fg >> 3, ks = fg & 7;
        float v0, v1;
        if (kind == 0) { int d0 = ks * 8 + tg; v0 = ts[blk * 8 + g][d0]; v1 = ts[blk * 8 + g][d0 + 4]; }
        else           { int s0 = ks * 8 + tg; v0 = ts[s0][blk * 8 + g]; v1 = ts[s0 + 4][blk * 8 + g]; }
        float2 o;
        o.x = __uint_as_float(f2tf32(v0));
        o.y = __uint_as_float(f2tf32(v1));
        *(float2*)(dst + ((size_t)fg * 32 + lane) * 2) = o;
    }
}

// ---------------------------------------------------------------------------
// Flash attention, tf32 mma. CTA = 128 q rows x (h,b). 8 warps, warp = 16 rows.
// K/V tiles double-buffered via cp.async; frag loads are conflict-free LDS.64.
// ---------------------------------------------------------------------------
__global__ __launch_bounds__(256, 1) void attn_mma_kernel(
    const float* __restrict__ bias, const float* __restrict__ gamma_f)
{
    extern __shared__ __align__(16) float sm[];   // 2 buffers x 8192 floats
    const int qt = blockIdx.x, h = blockIdx.y, b = blockIdx.z;
    const int bh = b * 8 + h;
    const int tid = threadIdx.x, wid = tid >> 5, lane = tid & 31;
    const int g = lane >> 2, tg = lane & 3;
    const float gamma = __ldg(gamma_f + h);

    // Q fragments in registers (once per CTA)
    uint32_t Qa[8][4];
    {
        const float* qp = g_q + ((size_t)bh * 2048 + qt * 128 + wid * 16) * 64;
#pragma unroll
        for (int ks = 0; ks < 8; ks++) {
            int d0 = ks * 8 + tg;
            Qa[ks][0] = f2tf32(qp[g * 64 + d0]);
            Qa[ks][1] = f2tf32(qp[(g + 8) * 64 + d0]);
            Qa[ks][2] = f2tf32(qp[g * 64 + d0 + 4]);
            Qa[ks][3] = f2tf32(qp[(g + 8) * 64 + d0 + 4]);
        }
    }

    float4 Oc[8];
#pragma unroll
    for (int j = 0; j < 8; j++) Oc[j] = make_float4(0.f, 0.f, 0.f, 0.f);
    float m0r = -1e30f, m1r = -1e30f, l0r = 0.f, l1r = 0.f;

    const float* ksrc = g_ksw + (size_t)bh * 32 * 4096;
    const float* vsrc = g_vsw + (size_t)bh * 32 * 4096;
    const float* bp = bias + ((size_t)b * 2048 + qt * 128 + wid * 16) * 2048;
    const unsigned char* mp = g_mask + b * 2048;

    // prefetch tile 0
    {
        float* dstb = sm;
#pragma unroll
        for (int i = 0; i < 4; i++) {
            cpasync16(dstb + (tid + i * 256) * 4, ksrc + (size_t)(tid + i * 256) * 4);
            cpasync16(dstb + 4096 + (tid + i * 256) * 4, vsrc + (size_t)(tid + i * 256) * 4);
        }
        cp_commit();
    }

    for (int kt = 0; kt < 32; kt++) {
        __syncthreads();                       // protect buffer being refilled
        if (kt + 1 < 32) {
            float* dstb = sm + ((kt + 1) & 1) * 8192;
            const float* kg = ksrc + (size_t)(kt + 1) * 4096;
            const float* vg = vsrc + (size_t)(kt + 1) * 4096;
#pragma unroll
            for (int i = 0; i < 4; i++) {
                cpasync16(dstb + (tid + i * 256) * 4, kg + (size_t)(tid + i * 256) * 4);
                cpasync16(dstb + 4096 + (tid + i * 256) * 4, vg + (size_t)(tid + i * 256) * 4);
            }
            cp_commit();
            cp_wait<1>();
        } else {
            cp_wait<0>();
        }
        __syncthreads();                       // tile kt visible to all warps

        const float* Kf = sm + (kt & 1) * 8192;
        const float* Vf = Kf + 4096;

        // bias + mask prefetch (L2-resident; issued before mma for MLP)
        float2 bR0[8], bR1[8];
        uchar2 mk[8];
        const float* bt = bp + kt * 64;
#pragma unroll
        for (int j = 0; j < 8; j++) {
            bR0[j] = *(const float2*)(bt + (size_t)g * 2048 + j * 8 + 2 * tg);
            bR1[j] = *(const float2*)(bt + (size_t)(g + 8) * 2048 + j * 8 + 2 * tg);
            mk[j] = *(const uchar2*)(mp + kt * 64 + j * 8 + 2 * tg);
        }

        // S = Q K^T
        float4 Sc[8];
#pragma unroll
        for (int j = 0; j < 8; j++) {
            float4 c = make_float4(0.f, 0.f, 0.f, 0.f);
#pragma unroll
            for (int ks = 0; ks < 8; ks++) {
                float2 kb = *(const float2*)(Kf + ((j * 8 + ks) * 32 + lane) * 2);
                mma8(c, Qa[ks], __float_as_uint(kb.x), __float_as_uint(kb.y));
            }
            c.x = mk[j].x ? -1e9f : fmaf(gamma, bR0[j].x, c.x);
            c.y = mk[j].y ? -1e9f : fmaf(gamma, bR0[j].y, c.y);
            c.z = mk[j].x ? -1e9f : fmaf(gamma, bR1[j].x, c.z);
            c.w = mk[j].y ? -1e9f : fmaf(gamma, bR1[j].y, c.w);
            Sc[j] = c;
        }

        // online softmax (rows g and g+8; quad lanes share a row)
        float tm0 = -1e30f, tm1 = -1e30f;
#pragma unroll
        for (int j = 0; j < 8; j++) {
            tm0 = fmaxf(tm0, fmaxf(Sc[j].x, Sc[j].y));
            tm1 = fmaxf(tm1, fmaxf(Sc[j].z, Sc[j].w));
        }
        tm0 = fmaxf(tm0, __shfl_xor_sync(0xffffffffu, tm0, 1));
        tm0 = fmaxf(tm0, __shfl_xor_sync(0xffffffffu, tm0, 2));
        tm1 = fmaxf(tm1, __shfl_xor_sync(0xffffffffu, tm1, 1));
        tm1 = fmaxf(tm1, __shfl_xor_sync(0xffffffffu, tm1, 2));
        const float mn0 = fmaxf(m0r, tm0), mn1 = fmaxf(m1r, tm1);
        const float sc0 = __expf(m0r - mn0), sc1 = __expf(m1r - mn1);
        m0r = mn0; m1r = mn1;
        float rs0 = 0.f, rs1 = 0.f;
#pragma unroll
        for (int j = 0; j < 8; j++) {
            Sc[j].x = __expf(Sc[j].x - mn0);
            Sc[j].y = __expf(Sc[j].y - mn0);
            Sc[j].z = __expf(Sc[j].z - mn1);
            Sc[j].w = __expf(Sc[j].w - mn1);
            rs0 += Sc[j].x + Sc[j].y;
            rs1 += Sc[j].z + Sc[j].w;
        }
        rs0 += __shfl_xor_sync(0xffffffffu, rs0, 1);
        rs0 += __shfl_xor_sync(0xffffffffu, rs0, 2);
        rs1 += __shfl_xor_sync(0xffffffffu, rs1, 1);
        rs1 += __shfl_xor_sync(0xffffffffu, rs1, 2);
        l0r = l0r * sc0 + rs0;
        l1r = l1r * sc1 + rs1;
#pragma unroll
        for (int j = 0; j < 8; j++) {
            Oc[j].x *= sc0; Oc[j].y *= sc0;
            Oc[j].z *= sc1; Oc[j].w *= sc1;
        }

        // re-fragment P: C-layout -> A-layout via quad shuffles
        uint32_t Pa[8][4];
        const int sA = (lane & ~3) | (tg >> 1);
        const int sB = sA + 2;
        const bool odd = tg & 1;
#pragma unroll
        for (int ks = 0; ks < 8; ks++) {
            float ex = __shfl_sync(0xffffffffu, Sc[ks].x, sA);
            float ey = __shfl_sync(0xffffffffu, Sc[ks].y, sA);
            float ez = __shfl_sync(0xffffffffu, Sc[ks].z, sA);
            float ew = __shfl_sync(0xffffffffu, Sc[ks].w, sA);
            float fx = __shfl_sync(0xffffffffu, Sc[ks].x, sB);
            float fy = __shfl_sync(0xffffffffu, Sc[ks].y, sB);
            float fz = __shfl_sync(0xffffffffu, Sc[ks].z, sB);
            float fw = __shfl_sync(0xffffffffu, Sc[ks].w, sB);
            Pa[ks][0] = f2tf32(odd ? ey : ex);
            Pa[ks][1] = f2tf32(odd ? ew : ez);
            Pa[ks][2] = f2tf32(odd ? fy : fx);
            Pa[ks][3] = f2tf32(odd ? fw : fz);
        }

        // O += P V
#pragma unroll
        for (int j = 0; j < 8; j++) {
#pragma unroll
            for (int ks = 0; ks < 8; ks++) {
                float2 vb = *(const float2*)(Vf + ((j * 8 + ks) * 32 + lane) * 2);
                mma8(Oc[j], Pa[ks], __float_as_uint(vb.x), __float_as_uint(vb.y));
            }
        }
    }

    const float inv0 = 1.f / l0r, inv1 = 1.f / l1r;
    float* op = g_att + ((size_t)b * 2048 + qt * 128 + wid * 16) * 512 + h * 64;
#pragma unroll
    for (int j = 0; j < 8; j++) {
        float2 o0 = make_float2(Oc[j].x * inv0, Oc[j].y * inv0);
        float2 o1 = make_float2(Oc[j].z * inv1, Oc[j].w * inv1);
        *(float2*)(op + (size_t)g * 512 + j * 8 + 2 * tg) = o0;
        *(float2*)(op + (size_t)(g + 8) * 512 + j * 8 + 2 * tg) = o1;
    }
}

// ---------------------------------------------------------------------------
// FF: y = x_p + (att @ Wff + bff)  (unchanged this round)
// ---------------------------------------------------------------------------
__global__ __launch_bounds__(256, 2) void ff_kernel(
    const float* __restrict__ Wff, const float* __restrict__ bff,
    const float* __restrict__ xp, float* __restrict__ out)
{
    const int nt = blockIdx.x;
    const int mt = blockIdx.y;
    const int ncol0 = nt * 128;

    __shared__ __align__(16) float As[8][132];
    __shared__ __align__(16) float Bs[8][128];

    const int tid = threadIdx.x;
    const int tx = tid & 15;
    const int ty = tid >> 4;
    const int m0 = mt * 128;

    const int a_row = tid >> 1;
    const int a_k   = (tid & 1) * 4;
    const int b_k   = tid >> 5;
    const int b_n   = (tid & 31) * 4;

    float c[8][8];
#pragma unroll
    for (int i = 0; i < 8; i++)
#pragma unroll
        for (int j = 0; j < 8; j++) c[i][j] = 0.f;

    for (int k0 = 0; k0 < 512; k0 += 8) {
        float4 av = *(const float4*)(g_att + (size_t)(m0 + a_row) * 512 + (k0 + a_k));
        As[a_k + 0][a_row] = av.x;
        As[a_k + 1][a_row] = av.y;
        As[a_k + 2][a_row] = av.z;
        As[a_k + 3][a_row] = av.w;
        *(float4*)(&Bs[b_k][b_n]) =
            *(const float4*)(Wff + (size_t)(k0 + b_k) * 512 + (ncol0 + b_n));
        __syncthreads();
#pragma unroll
        for (int kk = 0; kk < 8; kk++) {
            float4 a0 = *(const float4*)(&As[kk][ty * 4]);
            float4 a1 = *(const float4*)(&As[kk][64 + ty * 4]);
            float4 b0 = *(const float4*)(&Bs[kk][tx * 4]);
            float4 b1 = *(const float4*)(&Bs[kk][64 + tx * 4]);
            float am[8] = {a0.x, a0.y, a0.z, a0.w, a1.x, a1.y, a1.z, a1.w};
            float bn[8] = {b0.x, b0.y, b0.z, b0.w, b1.x, b1.y, b1.z, b1.w};
#pragma unroll
            for (int i = 0; i < 8; i++)
#pragma unroll
                for (int j = 0; j < 8; j++) c[i][j] += am[i] * bn[j];
        }
        __syncthreads();
    }
#pragma unroll
    for (int i = 0; i < 8; i++) {
        int r = m0 + (i >> 2) * 64 + ty * 4 + (i & 3);
#pragma unroll
        for (int js = 0; js < 2; js++) {
            int col = ncol0 + js * 64 + tx * 4;
            float4 bb = *(const float4*)(bff + col);
            float4 xx = *(const float4*)(xp + (size_t)r * 512 + col);
            float4 v;
            v.x = c[i][js * 4 + 0] + bb.x + xx.x;
            v.y = c[i][js * 4 + 1] + bb.y + xx.y;
            v.z = c[i][js * 4 + 2] + bb.z + xx.z;
            v.w = c[i][js * 4 + 3] + bb.w + xx.w;
            *(float4*)(out + (size_t)r * 512 + col) = v;
        }
    }
}

// ---------------------------------------------------------------------------
// LayerNorm in-place on d_out
// ---------------------------------------------------------------------------
__global__ __launch_bounds__(128) void ln_kernel(
    float* __restrict__ y, const float* __restrict__ g,
    const float* __restrict__ be)
{
    const int row = blockIdx.x;
    const int tid = threadIdx.x;
    float4 v = *(const float4*)(y + (size_t)row * 512 + tid * 4);
    float s = (v.x + v.y) + (v.z + v.w);
    float q = (v.x * v.x + v.y * v.y) + (v.z * v.z + v.w * v.w);
#pragma unroll
    for (int msk = 16; msk; msk >>= 1) {
        s += __shfl_xor_sync(0xffffffffu, s, msk);
        q += __shfl_xor_sync(0xffffffffu, q, msk);
    }
    __shared__ float ss[4], sq[4];
    const int w = tid >> 5;
    if ((tid & 31) == 0) { ss[w] = s; sq[w] = q; }
    __syncthreads();
    s = (ss[0] + ss[1]) + (ss[2] + ss[3]);
    q = (sq[0] + sq[1]) + (sq[2] + sq[3]);
    const float mu = s * (1.0f / 512.0f);
    const float var = q * (1.0f / 512.0f) - mu * mu;
    const float rs = rsqrtf(var + 1e-5f);
    float4 gg = *(const float4*)(g + tid * 4);
    float4 bb = *(const float4*)(be + tid * 4);
    float4 r;
    r.x = (v.x - mu) * rs * gg.x + bb.x;
    r.y = (v.y - mu) * rs * gg.y + bb.y;
    r.z = (v.z - mu) * rs * gg.z + bb.z;
    r.w = (v.w - mu) * rs * gg.w + bb.w;
    *(float4*)(y + (size_t)row * 512 + tid * 4) = r;
}

// ---------------------------------------------------------------------------
extern "C" void kernel_launch(void* const* d_in, const int* in_sizes, int n_in,
                              void* d_out, int out_size)
{
    const float* xp      = (const float*)d_in[0];
    const float* xpcre   = (const float*)d_in[1];
    const float* bias    = (const float*)d_in[2];
    const void*  mask    = d_in[3];
    const float* Wq      = (const float*)d_in[4];
    const float* Wkv     = (const float*)d_in[5];
    const float* Wff     = (const float*)d_in[6];
    const float* bff     = (const float*)d_in[7];
    const float* gamma_f = (const float*)d_in[8];
    const float* ln_g    = (const float*)d_in[9];
    const float* ln_b    = (const float*)d_in[10];
    float* out = (float*)d_out;

    const int attn_smem = 2 * 8192 * 4;   // 65536 B
    cudaFuncSetAttribute(attn_mma_kernel,
                         cudaFuncAttributeMaxDynamicSharedMemorySize, attn_smem);

    mask_norm_kernel<<<1, 256>>>(mask);

    dim3 pg(12, 128);
    proj_kernel<<<pg, 256>>>(xp, xpcre, Wq, Wkv);

    dim3 rg(32, 64, 2);
    repack_kv_kernel<<<rg, 256>>>();

    dim3 ag(16, 8, 8);   // (qtile128, h, b)
    attn_mma_kernel<<<ag, 256, attn_smem>>>(bias, gamma_f);

    dim3 fg(4, 128);
    ff_kernel<<<fg, 256>>>(Wff, bff, xp, out);

    ln_kernel<<<BB * SS, 128>>>(out, ln_g, ln_b);
}

// round 9
// speedup vs baseline: 3.0259x; 1.5249x over previous
#include <cuda_runtime.h>
#include <cuda_bf16.h>
#include <cstdint>

#define BB 8
#define SS 2048
#define DE 512
#define HH 8
#define DH 64

// Scratch (allocation-free: device globals)
__device__ float g_q[BB*HH*SS*DH];      // [b][h][s][d], pre-scaled by 1/8
__device__ float g_k[BB*HH*SS*DH];      // [b][h][s][d]
__device__ float g_v[BB*HH*SS*DH];      // [b][h][s][d]
__device__ float g_att[BB*SS*DE];       // [b][s][h*64+d]
__device__ unsigned char g_mask[BB*SS];
// Fragment-linear (mma B-frag) layouts: [bh][ktile][fraggrp(64)][lane(32)][2]
__device__ __align__(16) float g_ksw[BB*HH*32*4096];
__device__ __align__(16) float g_vsw[BB*HH*32*4096];

// ---------------------------------------------------------------------------
// small helpers
// ---------------------------------------------------------------------------
__device__ __forceinline__ uint32_t f2tf32(float f) {
    uint32_t u;
    asm("cvt.rna.tf32.f32 %0, %1;" : "=r"(u) : "f"(f));
    return u;
}
__device__ __forceinline__ void mma8(float4& c, const uint32_t a[4],
                                     uint32_t b0, uint32_t b1) {
    asm volatile(
        "mma.sync.aligned.m16n8k8.row.col.f32.tf32.tf32.f32 "
        "{%0,%1,%2,%3},{%4,%5,%6,%7},{%8,%9},{%0,%1,%2,%3};"
        : "+f"(c.x), "+f"(c.y), "+f"(c.z), "+f"(c.w)
        : "r"(a[0]), "r"(a[1]), "r"(a[2]), "r"(a[3]), "r"(b0), "r"(b1));
}
__device__ __forceinline__ void cpasync16(float* s, const float* g) {
    uint32_t sa = (uint32_t)__cvta_generic_to_shared(s);
    asm volatile("cp.async.cg.shared.global [%0], [%1], 16;" :: "r"(sa), "l"(g));
}
__device__ __forceinline__ void cp_commit() {
    asm volatile("cp.async.commit_group;" ::: "memory");
}
template <int N>
__device__ __forceinline__ void cp_wait() {
    asm volatile("cp.async.wait_group %0;" :: "n"(N) : "memory");
}

// ---------------------------------------------------------------------------
// Mask dtype probe + normalize
// ---------------------------------------------------------------------------
__global__ void mask_norm_kernel(const void* __restrict__ mraw)
{
    __shared__ int s_nz, s_3f;
    const int tid = threadIdx.x;
    if (tid == 0) { s_nz = 0; s_3f = 0; }
    __syncthreads();
    const unsigned char* u8 = (const unsigned char*)mraw;
    int nz = 0, c3 = 0;
    for (int i = tid; i < BB*SS; i += 256) {
        unsigned char c = u8[i];
        nz += (c != 0);
        c3 += (c == 0x3F);
    }
    atomicAdd(&s_nz, nz);
    atomicAdd(&s_3f, c3);
    __syncthreads();
    int mode = (s_3f > 100) ? 2 : ((s_nz > 1000) ? 0 : 1);
    for (int i = tid; i < BB*SS; i += 256) {
        unsigned char m;
        if (mode == 2)      m = (((const float*)mraw)[i] != 0.0f);
        else if (mode == 1) m = (((const int*)mraw)[i] != 0);
        else                m = (u8[i] != 0);
        g_mask[i] = m;
    }
}

// ===========================================================================
// tf32 GEMM core: CTA 128x128, K-step 16, double-buffered cp.async.
// 8 warps as 2(m)x4(n); warp tile m64 x n32.
// smem A: [m=128][k=16 pad 20]  (A-frag LDS banks 20g+tg: conflict-free)
// smem B: [k=16][n=128 pad 136] (B-frag LDS banks 8tg+g : conflict-free)
// ===========================================================================
#define STG_F (128*20 + 16*136)   // 4736 floats per stage

struct Frag16 {
    float4 c[4][4];
};

__device__ __forceinline__ void gemm_stage_load(
    float* Sa, const float* __restrict__ A, const float* __restrict__ W,
    int m0, int k0, int ldw, int wc0, int tid)
{
    float* Sb = Sa + 128*20;
#pragma unroll
    for (int i = 0; i < 2; i++) {
        int e = tid + i * 256;
        int row = e >> 2, kq = (e & 3) * 4;
        cpasync16(Sa + row * 20 + kq, A + (size_t)(m0 + row) * 512 + k0 + kq);
    }
#pragma unroll
    for (int i = 0; i < 2; i++) {
        int e = tid + i * 256;
        int row = e >> 5, nq = (e & 31) * 4;
        cpasync16(Sb + row * 136 + nq, W + (size_t)(k0 + row) * ldw + wc0 + nq);
    }
}

__device__ __forceinline__ void gemm_compute_stage(
    Frag16& F, const float* Sa, int wm, int wn, int g, int tg)
{
    const float* Sb = Sa + 128*20;
#pragma unroll
    for (int ks = 0; ks < 2; ks++) {
        uint32_t a[4][4];
#pragma unroll
        for (int mi = 0; mi < 4; mi++) {
            const float* ap = Sa + (wm * 64 + mi * 16) * 20 + ks * 8 + tg;
            a[mi][0] = f2tf32(ap[g * 20]);
            a[mi][1] = f2tf32(ap[(g + 8) * 20]);
            a[mi][2] = f2tf32(ap[g * 20 + 4]);
            a[mi][3] = f2tf32(ap[(g + 8) * 20 + 4]);
        }
        uint32_t bf[4][2];
#pragma unroll
        for (int ni = 0; ni < 4; ni++) {
            const float* bp = Sb + (ks * 8 + tg) * 136 + wn * 32 + ni * 8 + g;
            bf[ni][0] = f2tf32(bp[0]);
            bf[ni][1] = f2tf32(bp[4 * 136]);
        }
#pragma unroll
        for (int mi = 0; mi < 4; mi++)
#pragma unroll
            for (int ni = 0; ni < 4; ni++)
                mma8(F.c[mi][ni], a[mi], bf[ni][0], bf[ni][1]);
    }
}

// ---------------------------------------------------------------------------
// QKV projection, tf32 mma. grid (12 nt, 128 mt).
// ---------------------------------------------------------------------------
__global__ __launch_bounds__(256) void proj_tc_kernel(
    const float* __restrict__ xp, const float* __restrict__ xpcre,
    const float* __restrict__ Wq, const float* __restrict__ Wkv)
{
    extern __shared__ __align__(16) float sm[];
    const int nt = blockIdx.x, mt = blockIdx.y;
    const int grp = nt >> 2;
    const int ncol0 = (nt & 3) * 128;
    const float* __restrict__ A = (grp == 0) ? xp : xpcre;
    const float* __restrict__ W = (grp == 0) ? Wq : Wkv;
    const int ldw = (grp == 0) ? 512 : 1024;
    const int wc0 = (grp == 2) ? (512 + ncol0) : ncol0;
    float* dst = (grp == 0) ? g_q : ((grp == 1) ? g_k : g_v);
    const float osc = (grp == 0) ? 0.125f : 1.0f;

    const int tid = threadIdx.x, wid = tid >> 5, lane = tid & 31;
    const int g = lane >> 2, tg = lane & 3;
    const int wm = wid >> 2, wn = wid & 3;
    const int m0 = mt * 128;

    Frag16 F;
#pragma unroll
    for (int mi = 0; mi < 4; mi++)
#pragma unroll
        for (int ni = 0; ni < 4; ni++) F.c[mi][ni] = make_float4(0.f,0.f,0.f,0.f);

    gemm_stage_load(sm, A, W, m0, 0, ldw, wc0, tid);
    cp_commit();

    for (int kt = 0; kt < 32; kt++) {
        __syncthreads();
        if (kt + 1 < 32) {
            gemm_stage_load(sm + ((kt + 1) & 1) * STG_F, A, W, m0,
                            (kt + 1) * 16, ldw, wc0, tid);
            cp_commit();
            cp_wait<1>();
        } else {
            cp_wait<0>();
        }
        __syncthreads();
        gemm_compute_stage(F, sm + (kt & 1) * STG_F, wm, wn, g, tg);
    }

    // epilogue: strided per-head store
#pragma unroll
    for (int mi = 0; mi < 4; mi++) {
        int r0 = m0 + wm * 64 + mi * 16 + g;
        int r1 = r0 + 8;
        int b0 = r0 >> 11, s0 = r0 & 2047;
        int b1 = r1 >> 11, s1 = r1 & 2047;
#pragma unroll
        for (int ni = 0; ni < 4; ni++) {
            int col = ncol0 + wn * 32 + ni * 8 + 2 * tg;
            int h = col >> 6, d = col & 63;
            float4 c = F.c[mi][ni];
            float2 o0 = make_float2(c.x * osc, c.y * osc);
            float2 o1 = make_float2(c.z * osc, c.w * osc);
            *(float2*)(dst + ((size_t)(b0 * 8 + h) * 2048 + s0) * 64 + d) = o0;
            *(float2*)(dst + ((size_t)(b1 * 8 + h) * 2048 + s1) * 64 + d) = o1;
        }
    }
}

// ---------------------------------------------------------------------------
// FF, tf32 mma: y = x_p + att @ Wff + bff. grid (4 nt, 128 mt).
// ---------------------------------------------------------------------------
__global__ __launch_bounds__(256) void ff_tc_kernel(
    const float* __restrict__ Wff, const float* __restrict__ bff,
    const float* __restrict__ xp, float* __restrict__ out)
{
    extern __shared__ __align__(16) float sm[];
    const int nt = blockIdx.x, mt = blockIdx.y;
    const int ncol0 = nt * 128;
    const int tid = threadIdx.x, wid = tid >> 5, lane = tid & 31;
    const int g = lane >> 2, tg = lane & 3;
    const int wm = wid >> 2, wn = wid & 3;
    const int m0 = mt * 128;

    Frag16 F;
#pragma unroll
    for (int mi = 0; mi < 4; mi++)
#pragma unroll
        for (int ni = 0; ni < 4; ni++) F.c[mi][ni] = make_float4(0.f,0.f,0.f,0.f);

    gemm_stage_load(sm, g_att, Wff, m0, 0, 512, ncol0, tid);
    cp_commit();

    for (int kt = 0; kt < 32; kt++) {
        __syncthreads();
        if (kt + 1 < 32) {
            gemm_stage_load(sm + ((kt + 1) & 1) * STG_F, g_att, Wff, m0,
                            (kt + 1) * 16, 512, ncol0, tid);
            cp_commit();
            cp_wait<1>();
        } else {
            cp_wait<0>();
        }
        __syncthreads();
        gemm_compute_stage(F, sm + (kt & 1) * STG_F, wm, wn, g, tg);
    }

#pragma unroll
    for (int mi = 0; mi < 4; mi++) {
        int r0 = m0 + wm * 64 + mi * 16 + g;
        int r1 = r0 + 8;
#pragma unroll
        for (int ni = 0; ni < 4; ni++) {
            int col = ncol0 + wn * 32 + ni * 8 + 2 * tg;
            float4 c = F.c[mi][ni];
            float2 bb = *(const float2*)(bff + col);
            float2 x0 = *(const float2*)(xp + (size_t)r0 * 512 + col);
            float2 x1 = *(const float2*)(xp + (size_t)r1 * 512 + col);
            float2 o0 = make_float2(c.x + bb.x + x0.x, c.y + bb.y + x0.y);
            float2 o1 = make_float2(c.z + bb.x + x1.x, c.w + bb.y + x1.y);
            *(float2*)(out + (size_t)r0 * 512 + col) = o0;
            *(float2*)(out + (size_t)r1 * 512 + col) = o1;
        }
    }
}

// ---------------------------------------------------------------------------
// Repack K and V into mma-B-fragment-linear layout (+ round to tf32).
// ---------------------------------------------------------------------------
__global__ __launch_bounds__(256) void repack_kv_kernel()
{
    const int kt = blockIdx.x, bh = blockIdx.y, kind = blockIdx.z;
    __shared__ float ts[64][68];
    const float* src = (kind ? g_v : g_k) + ((size_t)bh * 2048 + kt * 64) * 64;
    const int tid = threadIdx.x;
#pragma unroll
    for (int r = 0; r < 4; r++) {
        int e = tid + r * 256;
        int row = e >> 4, c4 = (e & 15) * 4;
        float4 v = *(const float4*)(src + row * 64 + c4);
        ts[row][c4 + 0] = v.x; ts[row][c4 + 1] = v.y;
        ts[row][c4 + 2] = v.z; ts[row][c4 + 3] = v.w;
    }
    __syncthreads();
    const int w = tid >> 5, lane = tid & 31, g = lane >> 2, tg = lane & 3;
    float* dst = (kind ? g_vsw : g_ksw) + ((size_t)bh * 32 + kt) * 4096;
#pragma unroll
    for (int i = 0; i < 8; i++) {
        int fg = w * 8 + i;
        int blk = fg >> 3, ks = fg & 7;
        float v0, v1;
        if (kind == 0) { int d0 = ks * 8 + tg; v0 = ts[blk * 8 + g][d0]; v1 = ts[blk * 8 + g][d0 + 4]; }
        else           { int s0 = ks * 8 + tg; v0 = ts[s0][blk * 8 + g]; v1 = ts[s0 + 4][blk * 8 + g]; }
        float2 o;
        o.x = __uint_as_float(f2tf32(v0));
        o.y = __uint_as_float(f2tf32(v1));
        *(float2*)(dst + ((size_t)fg * 32 + lane) * 2) = o;
    }
}

// ---------------------------------------------------------------------------
// Flash attention, tf32 mma (unchanged from round 7)
// ---------------------------------------------------------------------------
__global__ __launch_bounds__(256, 1) void attn_mma_kernel(
    const float* __restrict__ bias, const float* __restrict__ gamma_f)
{
    extern __shared__ __align__(16) float sm[];   // 2 buffers x 8192 floats
    const int qt = blockIdx.x, h = blockIdx.y, b = blockIdx.z;
    const int bh = b * 8 + h;
    const int tid = threadIdx.x, wid = tid >> 5, lane = tid & 31;
    const int g = lane >> 2, tg = lane & 3;
    const float gamma = __ldg(gamma_f + h);

    uint32_t Qa[8][4];
    {
        const float* qp = g_q + ((size_t)bh * 2048 + qt * 128 + wid * 16) * 64;
#pragma unroll
        for (int ks = 0; ks < 8; ks++) {
            int d0 = ks * 8 + tg;
            Qa[ks][0] = f2tf32(qp[g * 64 + d0]);
            Qa[ks][1] = f2tf32(qp[(g + 8) * 64 + d0]);
            Qa[ks][2] = f2tf32(qp[g * 64 + d0 + 4]);
            Qa[ks][3] = f2tf32(qp[(g + 8) * 64 + d0 + 4]);
        }
    }

    float4 Oc[8];
#pragma unroll
    for (int j = 0; j < 8; j++) Oc[j] = make_float4(0.f, 0.f, 0.f, 0.f);
    float m0r = -1e30f, m1r = -1e30f, l0r = 0.f, l1r = 0.f;

    const float* ksrc = g_ksw + (size_t)bh * 32 * 4096;
    const float* vsrc = g_vsw + (size_t)bh * 32 * 4096;
    const float* bp = bias + ((size_t)b * 2048 + qt * 128 + wid * 16) * 2048;
    const unsigned char* mp = g_mask + b * 2048;

    {
        float* dstb = sm;
#pragma unroll
        for (int i = 0; i < 4; i++) {
            cpasync16(dstb + (tid + i * 256) * 4, ksrc + (size_t)(tid + i * 256) * 4);
            cpasync16(dstb + 4096 + (tid + i * 256) * 4, vsrc + (size_t)(tid + i * 256) * 4);
        }
        cp_commit();
    }

    for (int kt = 0; kt < 32; kt++) {
        __syncthreads();
        if (kt + 1 < 32) {
            float* dstb = sm + ((kt + 1) & 1) * 8192;
            const float* kg = ksrc + (size_t)(kt + 1) * 4096;
            const float* vg = vsrc + (size_t)(kt + 1) * 4096;
#pragma unroll
            for (int i = 0; i < 4; i++) {
                cpasync16(dstb + (tid + i * 256) * 4, kg + (size_t)(tid + i * 256) * 4);
                cpasync16(dstb + 4096 + (tid + i * 256) * 4, vg + (size_t)(tid + i * 256) * 4);
            }
            cp_commit();
            cp_wait<1>();
        } else {
            cp_wait<0>();
        }
        __syncthreads();

        const float* Kf = sm + (kt & 1) * 8192;
        const float* Vf = Kf + 4096;

        float2 bR0[8], bR1[8];
        uchar2 mk[8];
        const float* bt = bp + kt * 64;
#pragma unroll
        for (int j = 0; j < 8; j++) {
            bR0[j] = *(const float2*)(bt + (size_t)g * 2048 + j * 8 + 2 * tg);
            bR1[j] = *(const float2*)(bt + (size_t)(g + 8) * 2048 + j * 8 + 2 * tg);
            mk[j] = *(const uchar2*)(mp + kt * 64 + j * 8 + 2 * tg);
        }

        float4 Sc[8];
#pragma unroll
        for (int j = 0; j < 8; j++) {
            float4 c = make_float4(0.f, 0.f, 0.f, 0.f);
#pragma unroll
            for (int ks = 0; ks < 8; ks++) {
                float2 kb = *(const float2*)(Kf + ((j * 8 + ks) * 32 + lane) * 2);
                mma8(c, Qa[ks], __float_as_uint(kb.x), __float_as_uint(kb.y));
            }
            c.x = mk[j].x ? -1e9f : fmaf(gamma, bR0[j].x, c.x);
            c.y = mk[j].y ? -1e9f : fmaf(gamma, bR0[j].y, c.y);
            c.z = mk[j].x ? -1e9f : fmaf(gamma, bR1[j].x, c.z);
            c.w = mk[j].y ? -1e9f : fmaf(gamma, bR1[j].y, c.w);
            Sc[j] = c;
        }

        float tm0 = -1e30f, tm1 = -1e30f;
#pragma unroll
        for (int j = 0; j < 8; j++) {
            tm0 = fmaxf(tm0, fmaxf(Sc[j].x, Sc[j].y));
            tm1 = fmaxf(tm1, fmaxf(Sc[j].z, Sc[j].w));
        }
        tm0 = fmaxf(tm0, __shfl_xor_sync(0xffffffffu, tm0, 1));
        tm0 = fmaxf(tm0, __shfl_xor_sync(0xffffffffu, tm0, 2));
        tm1 = fmaxf(tm1, __shfl_xor_sync(0xffffffffu, tm1, 1));
        tm1 = fmaxf(tm1, __shfl_xor_sync(0xffffffffu, tm1, 2));
        const float mn0 = fmaxf(m0r, tm0), mn1 = fmaxf(m1r, tm1);
        const float sc0 = __expf(m0r - mn0), sc1 = __expf(m1r - mn1);
        m0r = mn0; m1r = mn1;
        float rs0 = 0.f, rs1 = 0.f;
#pragma unroll
        for (int j = 0; j < 8; j++) {
            Sc[j].x = __expf(Sc[j].x - mn0);
            Sc[j].y = __expf(Sc[j].y - mn0);
            Sc[j].z = __expf(Sc[j].z - mn1);
            Sc[j].w = __expf(Sc[j].w - mn1);
            rs0 += Sc[j].x + Sc[j].y;
            rs1 += Sc[j].z + Sc[j].w;
        }
        rs0 += __shfl_xor_sync(0xffffffffu, rs0, 1);
        rs0 += __shfl_xor_sync(0xffffffffu, rs0, 2);
        rs1 += __shfl_xor_sync(0xffffffffu, rs1, 1);
        rs1 += __shfl_xor_sync(0xffffffffu, rs1, 2);
        l0r = l0r * sc0 + rs0;
        l1r = l1r * sc1 + rs1;
#pragma unroll
        for (int j = 0; j < 8; j++) {
            Oc[j].x *= sc0; Oc[j].y *= sc0;
            Oc[j].z *= sc1; Oc[j].w *= sc1;
        }

        uint32_t Pa[8][4];
        const int sA = (lane & ~3) | (tg >> 1);
        const int sB = sA + 2;
        const bool odd = tg & 1;
#pragma unroll
        for (int ks = 0; ks < 8; ks++) {
            float ex = __shfl_sync(0xffffffffu, Sc[ks].x, sA);
            float ey = __shfl_sync(0xffffffffu, Sc[ks].y, sA);
            float ez = __shfl_sync(0xffffffffu, Sc[ks].z, sA);
            float ew = __shfl_sync(0xffffffffu, Sc[ks].w, sA);
            float fx = __shfl_sync(0xffffffffu, Sc[ks].x, sB);
            float fy = __shfl_sync(0xffffffffu, Sc[ks].y, sB);
            float fz = __shfl_sync(0xffffffffu, Sc[ks].z, sB);
            float fw = __shfl_sync(0xffffffffu, Sc[ks].w, sB);
            Pa[ks][0] = f2tf32(odd ? ey : ex);
            Pa[ks][1] = f2tf32(odd ? ew : ez);
            Pa[ks][2] = f2tf32(odd ? fy : fx);
            Pa[ks][3] = f2tf32(odd ? fw : fz);
        }

#pragma unroll
        for (int j = 0; j < 8; j++) {
#pragma unroll
            for (int ks = 0; ks < 8; ks++) {
                float2 vb = *(const float2*)(Vf + ((j * 8 + ks) * 32 + lane) * 2);
                mma8(Oc[j], Pa[ks], __float_as_uint(vb.x), __float_as_uint(vb.y));
            }
        }
    }

    const float inv0 = 1.f / l0r, inv1 = 1.f / l1r;
    float* op = g_att + ((size_t)b * 2048 + qt * 128 + wid * 16) * 512 + h * 64;
#pragma unroll
    for (int j = 0; j < 8; j++) {
        float2 o0 = make_float2(Oc[j].x * inv0, Oc[j].y * inv0);
        float2 o1 = make_float2(Oc[j].z * inv1, Oc[j].w * inv1);
        *(float2*)(op + (size_t)g * 512 + j * 8 + 2 * tg) = o0;
        *(float2*)(op + (size_t)(g + 8) * 512 + j * 8 + 2 * tg) = o1;
    }
}

// ---------------------------------------------------------------------------
// LayerNorm in-place on d_out
// ---------------------------------------------------------------------------
__global__ __launch_bounds__(128) void ln_kernel(
    float* __restrict__ y, const float* __restrict__ g,
    const float* __restrict__ be)
{
    const int row = blockIdx.x;
    const int tid = threadIdx.x;
    float4 v = *(const float4*)(y + (size_t)row * 512 + tid * 4);
    float s = (v.x + v.y) + (v.z + v.w);
    float q = (v.x * v.x + v.y * v.y) + (v.z * v.z + v.w * v.w);
#pragma unroll
    for (int msk = 16; msk; msk >>= 1) {
        s += __shfl_xor_sync(0xffffffffu, s, msk);
        q += __shfl_xor_sync(0xffffffffu, q, msk);
    }
    __shared__ float ss[4], sq[4];
    const int w = tid >> 5;
    if ((tid & 31) == 0) { ss[w] = s; sq[w] = q; }
    __syncthreads();
    s = (ss[0] + ss[1]) + (ss[2] + ss[3]);
    q = (sq[0] + sq[1]) + (sq[2] + sq[3]);
    const float mu = s * (1.0f / 512.0f);
    const float var = q * (1.0f / 512.0f) - mu * mu;
    const float rs = rsqrtf(var + 1e-5f);
    float4 gg = *(const float4*)(g + tid * 4);
    float4 bb = *(const float4*)(be + tid * 4);
    float4 r;
    r.x = (v.x - mu) * rs * gg.x + bb.x;
    r.y = (v.y - mu) * rs * gg.y + bb.y;
    r.z = (v.z - mu) * rs * gg.z + bb.z;
    r.w = (v.w - mu) * rs * gg.w + bb.w;
    *(float4*)(y + (size_t)row * 512 + tid * 4) = r;
}

// ---------------------------------------------------------------------------
extern "C" void kernel_launch(void* const* d_in, const int* in_sizes, int n_in,
                              void* d_out, int out_size)
{
    const float* xp      = (const float*)d_in[0];
    const float* xpcre   = (const float*)d_in[1];
    const float* bias    = (const float*)d_in[2];
    const void*  mask    = d_in[3];
    const float* Wq      = (const float*)d_in[4];
    const float* Wkv     = (const float*)d_in[5];
    const float* Wff     = (const float*)d_in[6];
    const float* bff     = (const float*)d_in[7];
    const float* gamma_f = (const float*)d_in[8];
    const float* ln_g    = (const float*)d_in[9];
    const float* ln_b    = (const float*)d_in[10];
    float* out = (float*)d_out;

    const int attn_smem = 2 * 8192 * 4;     // 65536 B
    const int gemm_smem = 2 * STG_F * 4;    // 37888 B
    cudaFuncSetAttribute(attn_mma_kernel,
                         cudaFuncAttributeMaxDynamicSharedMemorySize, attn_smem);
    cudaFuncSetAttribute(proj_tc_kernel,
                         cudaFuncAttributeMaxDynamicSharedMemorySize, gemm_smem);
    cudaFuncSetAttribute(ff_tc_kernel,
                         cudaFuncAttributeMaxDynamicSharedMemorySize, gemm_smem);

    mask_norm_kernel<<<1, 256>>>(mask);

    dim3 pg(12, 128);
    proj_tc_kernel<<<pg, 256, gemm_smem>>>(xp, xpcre, Wq, Wkv);

    dim3 rg(32, 64, 2);
    repack_kv_kernel<<<rg, 256>>>();

    dim3 ag(16, 8, 8);   // (qtile128, h, b)
    attn_mma_kernel<<<ag, 256, attn_smem>>>(bias, gamma_f);

    dim3 fg(4, 128);
    ff_tc_kernel<<<fg, 256, gemm_smem>>>(Wff, bff, xp, out);

    ln_kernel<<<BB * SS, 128>>>(out, ln_g, ln_b);
}

// round 12
// speedup vs baseline: 3.1781x; 1.0503x over previous
#include <cuda_runtime.h>
#include <cuda_bf16.h>
#include <cstdint>

#define BB 8
#define SS 2048
#define DE 512
#define HH 8
#define DH 64

// Scratch (allocation-free: device globals)
__device__ float g_q[BB*HH*SS*DH];      // [b][h][s][d], pre-scaled by 1/8
__device__ float g_k[BB*HH*SS*DH];      // [b][h][s][d]
__device__ float g_v[BB*HH*SS*DH];      // [b][h][s][d]
__device__ float g_att[BB*SS*DE];       // [b][s][h*64+d]
__device__ unsigned char g_mask[BB*SS];
// Pair-interleaved B-frag layout: [bh][ktile][fgpair(32)][lane(32)][4]
//   float4 = {fg even elem0, elem1, fg odd elem0, elem1}
__device__ __align__(16) float g_ksw[BB*HH*32*4096];
__device__ __align__(16) float g_vsw[BB*HH*32*4096];

// ---------------------------------------------------------------------------
// small helpers
// ---------------------------------------------------------------------------
__device__ __forceinline__ uint32_t f2tf32(float f) {
    uint32_t u;
    asm("cvt.rna.tf32.f32 %0, %1;" : "=r"(u) : "f"(f));
    return u;
}
__device__ __forceinline__ void mma8(float4& c, const uint32_t a[4],
                                     uint32_t b0, uint32_t b1) {
    asm volatile(
        "mma.sync.aligned.m16n8k8.row.col.f32.tf32.tf32.f32 "
        "{%0,%1,%2,%3},{%4,%5,%6,%7},{%8,%9},{%0,%1,%2,%3};"
        : "+f"(c.x), "+f"(c.y), "+f"(c.z), "+f"(c.w)
        : "r"(a[0]), "r"(a[1]), "r"(a[2]), "r"(a[3]), "r"(b0), "r"(b1));
}
__device__ __forceinline__ void cpasync16(float* s, const float* g) {
    uint32_t sa = (uint32_t)__cvta_generic_to_shared(s);
    asm volatile("cp.async.cg.shared.global [%0], [%1], 16;" :: "r"(sa), "l"(g));
}
__device__ __forceinline__ void cp_commit() {
    asm volatile("cp.async.commit_group;" ::: "memory");
}
template <int N>
__device__ __forceinline__ void cp_wait() {
    asm volatile("cp.async.wait_group %0;" :: "n"(N) : "memory");
}

// ---------------------------------------------------------------------------
// Mask dtype probe + normalize
// ---------------------------------------------------------------------------
__global__ void mask_norm_kernel(const void* __restrict__ mraw)
{
    __shared__ int s_nz, s_3f;
    const int tid = threadIdx.x;
    if (tid == 0) { s_nz = 0; s_3f = 0; }
    __syncthreads();
    const unsigned char* u8 = (const unsigned char*)mraw;
    int nz = 0, c3 = 0;
    for (int i = tid; i < BB*SS; i += 256) {
        unsigned char c = u8[i];
        nz += (c != 0);
        c3 += (c == 0x3F);
    }
    atomicAdd(&s_nz, nz);
    atomicAdd(&s_3f, c3);
    __syncthreads();
    int mode = (s_3f > 100) ? 2 : ((s_nz > 1000) ? 0 : 1);
    for (int i = tid; i < BB*SS; i += 256) {
        unsigned char m;
        if (mode == 2)      m = (((const float*)mraw)[i] != 0.0f);
        else if (mode == 1) m = (((const int*)mraw)[i] != 0);
        else                m = (u8[i] != 0);
        g_mask[i] = m;
    }
}

// ===========================================================================
// tf32 GEMM core (unchanged): CTA 128x128, K-step 16, double-buffered.
// ===========================================================================
#define STG_F (128*20 + 16*136)   // 4736 floats per stage

struct Frag16 {
    float4 c[4][4];
};

__device__ __forceinline__ void gemm_stage_load(
    float* Sa, const float* __restrict__ A, const float* __restrict__ W,
    int m0, int k0, int ldw, int wc0, int tid)
{
    float* Sb = Sa + 128*20;
#pragma unroll
    for (int i = 0; i < 2; i++) {
        int e = tid + i * 256;
        int row = e >> 2, kq = (e & 3) * 4;
        cpasync16(Sa + row * 20 + kq, A + (size_t)(m0 + row) * 512 + k0 + kq);
    }
#pragma unroll
    for (int i = 0; i < 2; i++) {
        int e = tid + i * 256;
        int row = e >> 5, nq = (e & 31) * 4;
        cpasync16(Sb + row * 136 + nq, W + (size_t)(k0 + row) * ldw + wc0 + nq);
    }
}

__device__ __forceinline__ void gemm_compute_stage(
    Frag16& F, const float* Sa, int wm, int wn, int g, int tg)
{
    const float* Sb = Sa + 128*20;
#pragma unroll
    for (int ks = 0; ks < 2; ks++) {
        uint32_t a[4][4];
#pragma unroll
        for (int mi = 0; mi < 4; mi++) {
            const float* ap = Sa + (wm * 64 + mi * 16) * 20 + ks * 8 + tg;
            a[mi][0] = f2tf32(ap[g * 20]);
            a[mi][1] = f2tf32(ap[(g + 8) * 20]);
            a[mi][2] = f2tf32(ap[g * 20 + 4]);
            a[mi][3] = f2tf32(ap[(g + 8) * 20 + 4]);
        }
        uint32_t bf[4][2];
#pragma unroll
        for (int ni = 0; ni < 4; ni++) {
            const float* bp = Sb + (ks * 8 + tg) * 136 + wn * 32 + ni * 8 + g;
            bf[ni][0] = f2tf32(bp[0]);
            bf[ni][1] = f2tf32(bp[4 * 136]);
        }
#pragma unroll
        for (int mi = 0; mi < 4; mi++)
#pragma unroll
            for (int ni = 0; ni < 4; ni++)
                mma8(F.c[mi][ni], a[mi], bf[ni][0], bf[ni][1]);
    }
}

// ---------------------------------------------------------------------------
// QKV projection, tf32 mma. grid (12 nt, 128 mt).
// ---------------------------------------------------------------------------
__global__ __launch_bounds__(256) void proj_tc_kernel(
    const float* __restrict__ xp, const float* __restrict__ xpcre,
    const float* __restrict__ Wq, const float* __restrict__ Wkv)
{
    extern __shared__ __align__(16) float sm[];
    const int nt = blockIdx.x, mt = blockIdx.y;
    const int grp = nt >> 2;
    const int ncol0 = (nt & 3) * 128;
    const float* __restrict__ A = (grp == 0) ? xp : xpcre;
    const float* __restrict__ W = (grp == 0) ? Wq : Wkv;
    const int ldw = (grp == 0) ? 512 : 1024;
    const int wc0 = (grp == 2) ? (512 + ncol0) : ncol0;
    float* dst = (grp == 0) ? g_q : ((grp == 1) ? g_k : g_v);
    const float osc = (grp == 0) ? 0.125f : 1.0f;

    const int tid = threadIdx.x, wid = tid >> 5, lane = tid & 31;
    const int g = lane >> 2, tg = lane & 3;
    const int wm = wid >> 2, wn = wid & 3;
    const int m0 = mt * 128;

    Frag16 F;
#pragma unroll
    for (int mi = 0; mi < 4; mi++)
#pragma unroll
        for (int ni = 0; ni < 4; ni++) F.c[mi][ni] = make_float4(0.f,0.f,0.f,0.f);

    gemm_stage_load(sm, A, W, m0, 0, ldw, wc0, tid);
    cp_commit();

    for (int kt = 0; kt < 32; kt++) {
        __syncthreads();
        if (kt + 1 < 32) {
            gemm_stage_load(sm + ((kt + 1) & 1) * STG_F, A, W, m0,
                            (kt + 1) * 16, ldw, wc0, tid);
            cp_commit();
            cp_wait<1>();
        } else {
            cp_wait<0>();
        }
        __syncthreads();
        gemm_compute_stage(F, sm + (kt & 1) * STG_F, wm, wn, g, tg);
    }

#pragma unroll
    for (int mi = 0; mi < 4; mi++) {
        int r0 = m0 + wm * 64 + mi * 16 + g;
        int r1 = r0 + 8;
        int b0 = r0 >> 11, s0 = r0 & 2047;
        int b1 = r1 >> 11, s1 = r1 & 2047;
#pragma unroll
        for (int ni = 0; ni < 4; ni++) {
            int col = ncol0 + wn * 32 + ni * 8 + 2 * tg;
            int h = col >> 6, d = col & 63;
            float4 c = F.c[mi][ni];
            float2 o0 = make_float2(c.x * osc, c.y * osc);
            float2 o1 = make_float2(c.z * osc, c.w * osc);
            *(float2*)(dst + ((size_t)(b0 * 8 + h) * 2048 + s0) * 64 + d) = o0;
            *(float2*)(dst + ((size_t)(b1 * 8 + h) * 2048 + s1) * 64 + d) = o1;
        }
    }
}

// ---------------------------------------------------------------------------
// FF, tf32 mma: y = x_p + att @ Wff + bff. grid (4 nt, 128 mt).
// ---------------------------------------------------------------------------
__global__ __launch_bounds__(256) void ff_tc_kernel(
    const float* __restrict__ Wff, const float* __restrict__ bff,
    const float* __restrict__ xp, float* __restrict__ out)
{
    extern __shared__ __align__(16) float sm[];
    const int nt = blockIdx.x, mt = blockIdx.y;
    const int ncol0 = nt * 128;
    const int tid = threadIdx.x, wid = tid >> 5, lane = tid & 31;
    const int g = lane >> 2, tg = lane & 3;
    const int wm = wid >> 2, wn = wid & 3;
    const int m0 = mt * 128;

    Frag16 F;
#pragma unroll
    for (int mi = 0; mi < 4; mi++)
#pragma unroll
        for (int ni = 0; ni < 4; ni++) F.c[mi][ni] = make_float4(0.f,0.f,0.f,0.f);

    gemm_stage_load(sm, g_att, Wff, m0, 0, 512, ncol0, tid);
    cp_commit();

    for (int kt = 0; kt < 32; kt++) {
        __syncthreads();
        if (kt + 1 < 32) {
            gemm_stage_load(sm + ((kt + 1) & 1) * STG_F, g_att, Wff, m0,
                            (kt + 1) * 16, 512, ncol0, tid);
            cp_commit();
            cp_wait<1>();
        } else {
            cp_wait<0>();
        }
        __syncthreads();
        gemm_compute_stage(F, sm + (kt & 1) * STG_F, wm, wn, g, tg);
    }

#pragma unroll
    for (int mi = 0; mi < 4; mi++) {
        int r0 = m0 + wm * 64 + mi * 16 + g;
        int r1 = r0 + 8;
#pragma unroll
        for (int ni = 0; ni < 4; ni++) {
            int col = ncol0 + wn * 32 + ni * 8 + 2 * tg;
            float4 c = F.c[mi][ni];
            float2 bb = *(const float2*)(bff + col);
            float2 x0 = *(const float2*)(xp + (size_t)r0 * 512 + col);
            float2 x1 = *(const float2*)(xp + (size_t)r1 * 512 + col);
            float2 o0 = make_float2(c.x + bb.x + x0.x, c.y + bb.y + x0.y);
            float2 o1 = make_float2(c.z + bb.x + x1.x, c.w + bb.y + x1.y);
            *(float2*)(out + (size_t)r0 * 512 + col) = o0;
            *(float2*)(out + (size_t)r1 * 512 + col) = o1;
        }
    }
}

// ---------------------------------------------------------------------------
// Repack K and V into PAIR-INTERLEAVED mma-B-fragment layout (+ tf32 round).
// fg = (blk*8 + ks); pair = fg>>1; store float2 at [pair][lane][(fg&1)*2].
// ---------------------------------------------------------------------------
__global__ __launch_bounds__(256) void repack_kv_kernel()
{
    const int kt = blockIdx.x, bh = blockIdx.y, kind = blockIdx.z;
    __shared__ float ts[64][68];
    const float* src = (kind ? g_v : g_k) + ((size_t)bh * 2048 + kt * 64) * 64;
    const int tid = threadIdx.x;
#pragma unroll
    for (int r = 0; r < 4; r++) {
        int e = tid + r * 256;
        int row = e >> 4, c4 = (e & 15) * 4;
        float4 v = *(const float4*)(src + row * 64 + c4);
        ts[row][c4 + 0] = v.x; ts[row][c4 + 1] = v.y;
        ts[row][c4 + 2] = v.z; ts[row][c4 + 3] = v.w;
    }
    __syncthreads();
    const int w = tid >> 5, lane = tid & 31, g = lane >> 2, tg = lane & 3;
    float* dst = (kind ? g_vsw : g_ksw) + ((size_t)bh * 32 + kt) * 4096;
#pragma unroll
    for (int i = 0; i < 8; i++) {
        int fg = w * 8 + i;
        int blk = fg >> 3, ks = fg & 7;
        float v0, v1;
        if (kind == 0) { int d0 = ks * 8 + tg; v0 = ts[blk * 8 + g][d0]; v1 = ts[blk * 8 + g][d0 + 4]; }
        else           { int s0 = ks * 8 + tg; v0 = ts[s0][blk * 8 + g]; v1 = ts[s0 + 4][blk * 8 + g]; }
        float2 o;
        o.x = __uint_as_float(f2tf32(v0));
        o.y = __uint_as_float(f2tf32(v1));
        *(float2*)(dst + (size_t)(fg >> 1) * 128 + lane * 4 + (fg & 1) * 2) = o;
    }
}

// ---------------------------------------------------------------------------
// Flash attention, tf32 mma. CTA = 4 warps x 32 q-rows = 128 rows.
// Warp m-tile 32 (two m16 halves share each B-frag LDS.128).
// ---------------------------------------------------------------------------
__global__ __launch_bounds__(128, 2) void attn_mma_kernel(
    const float* __restrict__ bias, const float* __restrict__ gamma_f)
{
    extern __shared__ __align__(16) float sm[];   // 2 stages x 8192 floats
    const int qt = blockIdx.x, h = blockIdx.y, b = blockIdx.z;
    const int bh = b * 8 + h;
    const int tid = threadIdx.x, wid = tid >> 5, lane = tid & 31;
    const int g = lane >> 2, tg = lane & 3;
    const float gamma = __ldg(gamma_f + h);

    // Q fragments: two m16 halves (rows wid*32 + [0,16))
    uint32_t Qa0[8][4], Qa1[8][4];
    {
        const float* qp = g_q + ((size_t)bh * 2048 + qt * 128 + wid * 32) * 64;
#pragma unroll
        for (int ks = 0; ks < 8; ks++) {
            int d0 = ks * 8 + tg;
            Qa0[ks][0] = f2tf32(qp[g * 64 + d0]);
            Qa0[ks][1] = f2tf32(qp[(g + 8) * 64 + d0]);
            Qa0[ks][2] = f2tf32(qp[g * 64 + d0 + 4]);
            Qa0[ks][3] = f2tf32(qp[(g + 8) * 64 + d0 + 4]);
            Qa1[ks][0] = f2tf32(qp[(g + 16) * 64 + d0]);
            Qa1[ks][1] = f2tf32(qp[(g + 24) * 64 + d0]);
            Qa1[ks][2] = f2tf32(qp[(g + 16) * 64 + d0 + 4]);
            Qa1[ks][3] = f2tf32(qp[(g + 24) * 64 + d0 + 4]);
        }
    }

    float4 Oc0[8], Oc1[8];
#pragma unroll
    for (int j = 0; j < 8; j++) {
        Oc0[j] = make_float4(0.f, 0.f, 0.f, 0.f);
        Oc1[j] = make_float4(0.f, 0.f, 0.f, 0.f);
    }
    float mr[4] = {-1e30f, -1e30f, -1e30f, -1e30f};
    float lr[4] = {0.f, 0.f, 0.f, 0.f};

    const float* ksrc = g_ksw + (size_t)bh * 32 * 4096;
    const float* vsrc = g_vsw + (size_t)bh * 32 * 4096;
    const float* bp = bias + ((size_t)b * 2048 + qt * 128 + wid * 32) * 2048;
    const unsigned char* mp = g_mask + b * 2048;

    // prefetch tile 0 (128 threads: 8 float4 each for K and V)
    {
#pragma unroll
        for (int i = 0; i < 8; i++) {
            cpasync16(sm + (tid + i * 128) * 4, ksrc + (size_t)(tid + i * 128) * 4);
            cpasync16(sm + 4096 + (tid + i * 128) * 4, vsrc + (size_t)(tid + i * 128) * 4);
        }
        cp_commit();
    }

    for (int kt = 0; kt < 32; kt++) {
        __syncthreads();
        if (kt + 1 < 32) {
            float* dstb = sm + ((kt + 1) & 1) * 8192;
            const float* kg = ksrc + (size_t)(kt + 1) * 4096;
            const float* vg = vsrc + (size_t)(kt + 1) * 4096;
#pragma unroll
            for (int i = 0; i < 8; i++) {
                cpasync16(dstb + (tid + i * 128) * 4, kg + (size_t)(tid + i * 128) * 4);
                cpasync16(dstb + 4096 + (tid + i * 128) * 4, vg + (size_t)(tid + i * 128) * 4);
            }
            cp_commit();
            cp_wait<1>();
        } else {
            cp_wait<0>();
        }
        __syncthreads();

        const float* Kf = sm + (kt & 1) * 8192;
        const float* Vf = Kf + 4096;
        const float* bt = bp + kt * 64;

        // S = Q K^T for both m16 halves; bias/mask applied per j-block
        float4 Sc0[8], Sc1[8];
#pragma unroll
        for (int j = 0; j < 8; j++) {
            uchar2 mk = *(const uchar2*)(mp + kt * 64 + j * 8 + 2 * tg);
            float2 b0 = *(const float2*)(bt + (size_t)g * 2048 + j * 8 + 2 * tg);
            float2 b1 = *(const float2*)(bt + (size_t)(g + 8) * 2048 + j * 8 + 2 * tg);
            float2 b2 = *(const float2*)(bt + (size_t)(g + 16) * 2048 + j * 8 + 2 * tg);
            float2 b3 = *(const float2*)(bt + (size_t)(g + 24) * 2048 + j * 8 + 2 * tg);
            float4 c0 = make_float4(0.f, 0.f, 0.f, 0.f);
            float4 c1 = make_float4(0.f, 0.f, 0.f, 0.f);
#pragma unroll
            for (int kp = 0; kp < 4; kp++) {
                float4 kb = *(const float4*)(Kf + (j * 4 + kp) * 128 + lane * 4);
                mma8(c0, Qa0[2 * kp],     __float_as_uint(kb.x), __float_as_uint(kb.y));
                mma8(c1, Qa1[2 * kp],     __float_as_uint(kb.x), __float_as_uint(kb.y));
                mma8(c0, Qa0[2 * kp + 1], __float_as_uint(kb.z), __float_as_uint(kb.w));
                mma8(c1, Qa1[2 * kp + 1], __float_as_uint(kb.z), __float_as_uint(kb.w));
            }
            c0.x = mk.x ? -1e9f : fmaf(gamma, b0.x, c0.x);
            c0.y = mk.y ? -1e9f : fmaf(gamma, b0.y, c0.y);
            c0.z = mk.x ? -1e9f : fmaf(gamma, b1.x, c0.z);
            c0.w = mk.y ? -1e9f : fmaf(gamma, b1.y, c0.w);
            c1.x = mk.x ? -1e9f : fmaf(gamma, b2.x, c1.x);
            c1.y = mk.y ? -1e9f : fmaf(gamma, b2.y, c1.y);
            c1.z = mk.x ? -1e9f : fmaf(gamma, b3.x, c1.z);
            c1.w = mk.y ? -1e9f : fmaf(gamma, b3.y, c1.w);
            Sc0[j] = c0;
            Sc1[j] = c1;
        }

        // online softmax over 4 row-groups (quad lanes share rows)
        float tm[4] = {-1e30f, -1e30f, -1e30f, -1e30f};
#pragma unroll
        for (int j = 0; j < 8; j++) {
            tm[0] = fmaxf(tm[0], fmaxf(Sc0[j].x, Sc0[j].y));
            tm[1] = fmaxf(tm[1], fmaxf(Sc0[j].z, Sc0[j].w));
            tm[2] = fmaxf(tm[2], fmaxf(Sc1[j].x, Sc1[j].y));
            tm[3] = fmaxf(tm[3], fmaxf(Sc1[j].z, Sc1[j].w));
        }
        float sc[4];
#pragma unroll
        for (int r = 0; r < 4; r++) {
            tm[r] = fmaxf(tm[r], __shfl_xor_sync(0xffffffffu, tm[r], 1));
            tm[r] = fmaxf(tm[r], __shfl_xor_sync(0xffffffffu, tm[r], 2));
            float mn = fmaxf(mr[r], tm[r]);
            sc[r] = __expf(mr[r] - mn);
            mr[r] = mn;
        }
        float rs[4] = {0.f, 0.f, 0.f, 0.f};
#pragma unroll
        for (int j = 0; j < 8; j++) {
            Sc0[j].x = __expf(Sc0[j].x - mr[0]);
            Sc0[j].y = __expf(Sc0[j].y - mr[0]);
            Sc0[j].z = __expf(Sc0[j].z - mr[1]);
            Sc0[j].w = __expf(Sc0[j].w - mr[1]);
            Sc1[j].x = __expf(Sc1[j].x - mr[2]);
            Sc1[j].y = __expf(Sc1[j].y - mr[2]);
            Sc1[j].z = __expf(Sc1[j].z - mr[3]);
            Sc1[j].w = __expf(Sc1[j].w - mr[3]);
            rs[0] += Sc0[j].x + Sc0[j].y;
            rs[1] += Sc0[j].z + Sc0[j].w;
            rs[2] += Sc1[j].x + Sc1[j].y;
            rs[3] += Sc1[j].z + Sc1[j].w;
        }
#pragma unroll
        for (int r = 0; r < 4; r++) {
            rs[r] += __shfl_xor_sync(0xffffffffu, rs[r], 1);
            rs[r] += __shfl_xor_sync(0xffffffffu, rs[r], 2);
            lr[r] = lr[r] * sc[r] + rs[r];
        }
#pragma unroll
        for (int j = 0; j < 8; j++) {
            Oc0[j].x *= sc[0]; Oc0[j].y *= sc[0];
            Oc0[j].z *= sc[1]; Oc0[j].w *= sc[1];
            Oc1[j].x *= sc[2]; Oc1[j].y *= sc[2];
            Oc1[j].z *= sc[3]; Oc1[j].w *= sc[3];
        }

        // re-fragment P (C-layout -> A-layout) via quad shuffles, both halves
        uint32_t Pa0[8][4], Pa1[8][4];
        const int sA = (lane & ~3) | (tg >> 1);
        const int sB = sA + 2;
        const bool odd = tg & 1;
#pragma unroll
        for (int ks = 0; ks < 8; ks++) {
            float ex = __shfl_sync(0xffffffffu, Sc0[ks].x, sA);
            float ey = __shfl_sync(0xffffffffu, Sc0[ks].y, sA);
            float ez = __shfl_sync(0xffffffffu, Sc0[ks].z, sA);
            float ew = __shfl_sync(0xffffffffu, Sc0[ks].w, sA);
            float fx = __shfl_sync(0xffffffffu, Sc0[ks].x, sB);
            float fy = __shfl_sync(0xffffffffu, Sc0[ks].y, sB);
            float fz = __shfl_sync(0xffffffffu, Sc0[ks].z, sB);
            float fw = __shfl_sync(0xffffffffu, Sc0[ks].w, sB);
            Pa0[ks][0] = f2tf32(odd ? ey : ex);
            Pa0[ks][1] = f2tf32(odd ? ew : ez);
            Pa0[ks][2] = f2tf32(odd ? fy : fx);
            Pa0[ks][3] = f2tf32(odd ? fw : fz);
            ex = __shfl_sync(0xffffffffu, Sc1[ks].x, sA);
            ey = __shfl_sync(0xffffffffu, Sc1[ks].y, sA);
            ez = __shfl_sync(0xffffffffu, Sc1[ks].z, sA);
            ew = __shfl_sync(0xffffffffu, Sc1[ks].w, sA);
            fx = __shfl_sync(0xffffffffu, Sc1[ks].x, sB);
            fy = __shfl_sync(0xffffffffu, Sc1[ks].y, sB);
            fz = __shfl_sync(0xffffffffu, Sc1[ks].z, sB);
            fw = __shfl_sync(0xffffffffu, Sc1[ks].w, sB);
            Pa1[ks][0] = f2tf32(odd ? ey : ex);
            Pa1[ks][1] = f2tf32(odd ? ew : ez);
            Pa1[ks][2] = f2tf32(odd ? fy : fx);
            Pa1[ks][3] = f2tf32(odd ? fw : fz);
        }

        // O += P V (shared V-frag LDS.128 feeds both halves)
#pragma unroll
        for (int j = 0; j < 8; j++) {
#pragma unroll
            for (int kp = 0; kp < 4; kp++) {
                float4 vb = *(const float4*)(Vf + (j * 4 + kp) * 128 + lane * 4);
                mma8(Oc0[j], Pa0[2 * kp],     __float_as_uint(vb.x), __float_as_uint(vb.y));
                mma8(Oc1[j], Pa1[2 * kp],     __float_as_uint(vb.x), __float_as_uint(vb.y));
                mma8(Oc0[j], Pa0[2 * kp + 1], __float_as_uint(vb.z), __float_as_uint(vb.w));
                mma8(Oc1[j], Pa1[2 * kp + 1], __float_as_uint(vb.z), __float_as_uint(vb.w));
            }
        }
    }

    const float i0 = 1.f / lr[0], i1 = 1.f / lr[1];
    const float i2 = 1.f / lr[2], i3 = 1.f / lr[3];
    float* op = g_att + ((size_t)b * 2048 + qt * 128 + wid * 32) * 512 + h * 64;
#pragma unroll
    for (int j = 0; j < 8; j++) {
        int col = j * 8 + 2 * tg;
        *(float2*)(op + (size_t)g * 512 + col) =
            make_float2(Oc0[j].x * i0, Oc0[j].y * i0);
        *(float2*)(op + (size_t)(g + 8) * 512 + col) =
            make_float2(Oc0[j].z * i1, Oc0[j].w * i1);
        *(float2*)(op + (size_t)(g + 16) * 512 + col) =
            make_float2(Oc1[j].x * i2, Oc1[j].y * i2);
        *(float2*)(op + (size_t)(g + 24) * 512 + col) =
            make_float2(Oc1[j].z * i3, Oc1[j].w * i3);
    }
}

// ---------------------------------------------------------------------------
// LayerNorm in-place on d_out
// ---------------------------------------------------------------------------
__global__ __launch_bounds__(128) void ln_kernel(
    float* __restrict__ y, const float* __restrict__ g,
    const float* __restrict__ be)
{
    const int row = blockIdx.x;
    const int tid = threadIdx.x;
    float4 v = *(const float4*)(y + (size_t)row * 512 + tid * 4);
    float s = (v.x + v.y) + (v.z + v.w);
    float q = (v.x * v.x + v.y * v.y) + (v.z * v.z + v.w * v.w);
#pragma unroll
    for (int msk = 16; msk; msk >>= 1) {
        s += __shfl_xor_sync(0xffffffffu, s, msk);
        q += __shfl_xor_sync(0xffffffffu, q, msk);
    }
    __shared__ float ss[4], sq[4];
    const int w = tid >> 5;
    if ((tid & 31) == 0) { ss[w] = s; sq[w] = q; }
    __syncthreads();
    s = (ss[0] + ss[1]) + (ss[2] + ss[3]);
    q = (sq[0] + sq[1]) + (sq[2] + sq[3]);
    const float mu = s * (1.0f / 512.0f);
    const float var = q * (1.0f / 512.0f) - mu * mu;
    const float rs = rsqrtf(var + 1e-5f);
    float4 gg = *(const float4*)(g + tid * 4);
    float4 bb = *(const float4*)(be + tid * 4);
    float4 r;
    r.x = (v.x - mu) * rs * gg.x + bb.x;
    r.y = (v.y - mu) * rs * gg.y + bb.y;
    r.z = (v.z - mu) * rs * gg.z + bb.z;
    r.w = (v.w - mu) * rs * gg.w + bb.w;
    *(float4*)(y + (size_t)row * 512 + tid * 4) = r;
}

// ---------------------------------------------------------------------------
extern "C" void kernel_launch(void* const* d_in, const int* in_sizes, int n_in,
                              void* d_out, int out_size)
{
    const float* xp      = (const float*)d_in[0];
    const float* xpcre   = (const float*)d_in[1];
    const float* bias    = (const float*)d_in[2];
    const void*  mask    = d_in[3];
    const float* Wq      = (const float*)d_in[4];
    const float* Wkv     = (const float*)d_in[5];
    const float* Wff     = (const float*)d_in[6];
    const float* bff     = (const float*)d_in[7];
    const float* gamma_f = (const float*)d_in[8];
    const float* ln_g    = (const float*)d_in[9];
    const float* ln_b    = (const float*)d_in[10];
    float* out = (float*)d_out;

    const int attn_smem = 2 * 8192 * 4;     // 65536 B
    const int gemm_smem = 2 * STG_F * 4;    // 37888 B
    cudaFuncSetAttribute(attn_mma_kernel,
                         cudaFuncAttributeMaxDynamicSharedMemorySize, attn_smem);
    cudaFuncSetAttribute(proj_tc_kernel,
                         cudaFuncAttributeMaxDynamicSharedMemorySize, gemm_smem);
    cudaFuncSetAttribute(ff_tc_kernel,
                         cudaFuncAttributeMaxDynamicSharedMemorySize, gemm_smem);

    mask_norm_kernel<<<1, 256>>>(mask);

    dim3 pg(12, 128);
    proj_tc_kernel<<<pg, 256, gemm_smem>>>(xp, xpcre, Wq, Wkv);

    dim3 rg(32, 64, 2);
    repack_kv_kernel<<<rg, 256>>>();

    dim3 ag(16, 8, 8);   // (qtile128, h, b), 4 warps x 32 rows
    attn_mma_kernel<<<ag, 128, attn_smem>>>(bias, gamma_f);

    dim3 fg(4, 128);
    ff_tc_kernel<<<fg, 256, gemm_smem>>>(Wff, bff, xp, out);

    ln_kernel<<<BB * SS, 128>>>(out, ln_g, ln_b);
}

// round 14
// speedup vs baseline: 4.5339x; 1.4266x over previous
#include <cuda_runtime.h>
#include <cuda_bf16.h>
#include <cstdint>

#define BB 8
#define SS 2048
#define DE 512
#define HH 8
#define DH 64

// Scratch (allocation-free: device globals)
__device__ float g_q[BB*HH*SS*DH];      // [b][h][s][d], pre-scaled by 1/8
__device__ float g_k[BB*HH*SS*DH];      // [b][h][s][d]
__device__ float g_v[BB*HH*SS*DH];      // [b][h][s][d]
__device__ float g_att[BB*SS*DE];       // [b][s][h*64+d]
__device__ unsigned char g_mask[BB*SS];
// bf16 m16n8k16 B-fragment layout per 64x64 tile:
//   [fg(16)=(blk8,kc2)][lane(32)][4 u32], u32 r = (kchunk=kc2*2+(r>>1), reg=r&1)
__device__ __align__(16) uint32_t g_ksw[BB*HH*32*2048];
__device__ __align__(16) uint32_t g_vsw[BB*HH*32*2048];

// ---------------------------------------------------------------------------
// small helpers
// ---------------------------------------------------------------------------
__device__ __forceinline__ uint32_t f2tf32(float f) {
    uint32_t u;
    asm("cvt.rna.tf32.f32 %0, %1;" : "=r"(u) : "f"(f));
    return u;
}
// pack two floats to bf16x2: lo = a (element 0), hi = b (element 1)
__device__ __forceinline__ uint32_t pkbf(float lo, float hi) {
    uint32_t r;
    asm("cvt.rn.bf16x2.f32 %0, %1, %2;" : "=r"(r) : "f"(hi), "f"(lo));
    return r;
}
__device__ __forceinline__ void mma8(float4& c, const uint32_t a[4],
                                     uint32_t b0, uint32_t b1) {
    asm volatile(
        "mma.sync.aligned.m16n8k8.row.col.f32.tf32.tf32.f32 "
        "{%0,%1,%2,%3},{%4,%5,%6,%7},{%8,%9},{%0,%1,%2,%3};"
        : "+f"(c.x), "+f"(c.y), "+f"(c.z), "+f"(c.w)
        : "r"(a[0]), "r"(a[1]), "r"(a[2]), "r"(a[3]), "r"(b0), "r"(b1));
}
__device__ __forceinline__ void mma16(float4& c, const uint32_t a[4],
                                      uint32_t b0, uint32_t b1) {
    asm volatile(
        "mma.sync.aligned.m16n8k16.row.col.f32.bf16.bf16.f32 "
        "{%0,%1,%2,%3},{%4,%5,%6,%7},{%8,%9},{%0,%1,%2,%3};"
        : "+f"(c.x), "+f"(c.y), "+f"(c.z), "+f"(c.w)
        : "r"(a[0]), "r"(a[1]), "r"(a[2]), "r"(a[3]), "r"(b0), "r"(b1));
}
__device__ __forceinline__ void cpasync16(void* s, const void* g) {
    uint32_t sa = (uint32_t)__cvta_generic_to_shared(s);
    asm volatile("cp.async.cg.shared.global [%0], [%1], 16;" :: "r"(sa), "l"(g));
}
__device__ __forceinline__ void cp_commit() {
    asm volatile("cp.async.commit_group;" ::: "memory");
}
template <int N>
__device__ __forceinline__ void cp_wait() {
    asm volatile("cp.async.wait_group %0;" :: "n"(N) : "memory");
}

// ---------------------------------------------------------------------------
// Mask dtype probe + normalize
// ---------------------------------------------------------------------------
__global__ void mask_norm_kernel(const void* __restrict__ mraw)
{
    __shared__ int s_nz, s_3f;
    const int tid = threadIdx.x;
    if (tid == 0) { s_nz = 0; s_3f = 0; }
    __syncthreads();
    const unsigned char* u8 = (const unsigned char*)mraw;
    int nz = 0, c3 = 0;
    for (int i = tid; i < BB*SS; i += 256) {
        unsigned char c = u8[i];
        nz += (c != 0);
        c3 += (c == 0x3F);
    }
    atomicAdd(&s_nz, nz);
    atomicAdd(&s_3f, c3);
    __syncthreads();
    int mode = (s_3f > 100) ? 2 : ((s_nz > 1000) ? 0 : 1);
    for (int i = tid; i < BB*SS; i += 256) {
        unsigned char m;
        if (mode == 2)      m = (((const float*)mraw)[i] != 0.0f);
        else if (mode == 1) m = (((const int*)mraw)[i] != 0);
        else                m = (u8[i] != 0);
        g_mask[i] = m;
    }
}

// ===========================================================================
// tf32 GEMM core (unchanged): CTA 128x128, K-step 16, double-buffered.
// ===========================================================================
#define STG_F (128*20 + 16*136)   // 4736 floats per stage

struct Frag16 {
    float4 c[4][4];
};

__device__ __forceinline__ void gemm_stage_load(
    float* Sa, const float* __restrict__ A, const float* __restrict__ W,
    int m0, int k0, int ldw, int wc0, int tid)
{
    float* Sb = Sa + 128*20;
#pragma unroll
    for (int i = 0; i < 2; i++) {
        int e = tid + i * 256;
        int row = e >> 2, kq = (e & 3) * 4;
        cpasync16(Sa + row * 20 + kq, A + (size_t)(m0 + row) * 512 + k0 + kq);
    }
#pragma unroll
    for (int i = 0; i < 2; i++) {
        int e = tid + i * 256;
        int row = e >> 5, nq = (e & 31) * 4;
        cpasync16(Sb + row * 136 + nq, W + (size_t)(k0 + row) * ldw + wc0 + nq);
    }
}

__device__ __forceinline__ void gemm_compute_stage(
    Frag16& F, const float* Sa, int wm, int wn, int g, int tg)
{
    const float* Sb = Sa + 128*20;
#pragma unroll
    for (int ks = 0; ks < 2; ks++) {
        uint32_t a[4][4];
#pragma unroll
        for (int mi = 0; mi < 4; mi++) {
            const float* ap = Sa + (wm * 64 + mi * 16) * 20 + ks * 8 + tg;
            a[mi][0] = f2tf32(ap[g * 20]);
            a[mi][1] = f2tf32(ap[(g + 8) * 20]);
            a[mi][2] = f2tf32(ap[g * 20 + 4]);
            a[mi][3] = f2tf32(ap[(g + 8) * 20 + 4]);
        }
        uint32_t bf[4][2];
#pragma unroll
        for (int ni = 0; ni < 4; ni++) {
            const float* bp = Sb + (ks * 8 + tg) * 136 + wn * 32 + ni * 8 + g;
            bf[ni][0] = f2tf32(bp[0]);
            bf[ni][1] = f2tf32(bp[4 * 136]);
        }
#pragma unroll
        for (int mi = 0; mi < 4; mi++)
#pragma unroll
            for (int ni = 0; ni < 4; ni++)
                mma8(F.c[mi][ni], a[mi], bf[ni][0], bf[ni][1]);
    }
}

// ---------------------------------------------------------------------------
// QKV projection, tf32 mma. grid (12 nt, 128 mt).
// ---------------------------------------------------------------------------
__global__ __launch_bounds__(256) void proj_tc_kernel(
    const float* __restrict__ xp, const float* __restrict__ xpcre,
    const float* __restrict__ Wq, const float* __restrict__ Wkv)
{
    extern __shared__ __align__(16) float sm[];
    const int nt = blockIdx.x, mt = blockIdx.y;
    const int grp = nt >> 2;
    const int ncol0 = (nt & 3) * 128;
    const float* __restrict__ A = (grp == 0) ? xp : xpcre;
    const float* __restrict__ W = (grp == 0) ? Wq : Wkv;
    const int ldw = (grp == 0) ? 512 : 1024;
    const int wc0 = (grp == 2) ? (512 + ncol0) : ncol0;
    float* dst = (grp == 0) ? g_q : ((grp == 1) ? g_k : g_v);
    const float osc = (grp == 0) ? 0.125f : 1.0f;

    const int tid = threadIdx.x, wid = tid >> 5, lane = tid & 31;
    const int g = lane >> 2, tg = lane & 3;
    const int wm = wid >> 2, wn = wid & 3;
    const int m0 = mt * 128;

    Frag16 F;
#pragma unroll
    for (int mi = 0; mi < 4; mi++)
#pragma unroll
        for (int ni = 0; ni < 4; ni++) F.c[mi][ni] = make_float4(0.f,0.f,0.f,0.f);

    gemm_stage_load(sm, A, W, m0, 0, ldw, wc0, tid);
    cp_commit();

    for (int kt = 0; kt < 32; kt++) {
        __syncthreads();
        if (kt + 1 < 32) {
            gemm_stage_load(sm + ((kt + 1) & 1) * STG_F, A, W, m0,
                            (kt + 1) * 16, ldw, wc0, tid);
            cp_commit();
            cp_wait<1>();
        } else {
            cp_wait<0>();
        }
        __syncthreads();
        gemm_compute_stage(F, sm + (kt & 1) * STG_F, wm, wn, g, tg);
    }

#pragma unroll
    for (int mi = 0; mi < 4; mi++) {
        int r0 = m0 + wm * 64 + mi * 16 + g;
        int r1 = r0 + 8;
        int b0 = r0 >> 11, s0 = r0 & 2047;
        int b1 = r1 >> 11, s1 = r1 & 2047;
#pragma unroll
        for (int ni = 0; ni < 4; ni++) {
            int col = ncol0 + wn * 32 + ni * 8 + 2 * tg;
            int h = col >> 6, d = col & 63;
            float4 c = F.c[mi][ni];
            float2 o0 = make_float2(c.x * osc, c.y * osc);
            float2 o1 = make_float2(c.z * osc, c.w * osc);
            *(float2*)(dst + ((size_t)(b0 * 8 + h) * 2048 + s0) * 64 + d) = o0;
            *(float2*)(dst + ((size_t)(b1 * 8 + h) * 2048 + s1) * 64 + d) = o1;
        }
    }
}

// ---------------------------------------------------------------------------
// FF, tf32 mma: y = x_p + att @ Wff + bff. grid (4 nt, 128 mt).
// ---------------------------------------------------------------------------
__global__ __launch_bounds__(256) void ff_tc_kernel(
    const float* __restrict__ Wff, const float* __restrict__ bff,
    const float* __restrict__ xp, float* __restrict__ out)
{
    extern __shared__ __align__(16) float sm[];
    const int nt = blockIdx.x, mt = blockIdx.y;
    const int ncol0 = nt * 128;
    const int tid = threadIdx.x, wid = tid >> 5, lane = tid & 31;
    const int g = lane >> 2, tg = lane & 3;
    const int wm = wid >> 2, wn = wid & 3;
    const int m0 = mt * 128;

    Frag16 F;
#pragma unroll
    for (int mi = 0; mi < 4; mi++)
#pragma unroll
        for (int ni = 0; ni < 4; ni++) F.c[mi][ni] = make_float4(0.f,0.f,0.f,0.f);

    gemm_stage_load(sm, g_att, Wff, m0, 0, 512, ncol0, tid);
    cp_commit();

    for (int kt = 0; kt < 32; kt++) {
        __syncthreads();
        if (kt + 1 < 32) {
            gemm_stage_load(sm + ((kt + 1) & 1) * STG_F, g_att, Wff, m0,
                            (kt + 1) * 16, 512, ncol0, tid);
            cp_commit();
            cp_wait<1>();
        } else {
            cp_wait<0>();
        }
        __syncthreads();
        gemm_compute_stage(F, sm + (kt & 1) * STG_F, wm, wn, g, tg);
    }

#pragma unroll
    for (int mi = 0; mi < 4; mi++) {
        int r0 = m0 + wm * 64 + mi * 16 + g;
        int r1 = r0 + 8;
#pragma unroll
        for (int ni = 0; ni < 4; ni++) {
            int col = ncol0 + wn * 32 + ni * 8 + 2 * tg;
            float4 c = F.c[mi][ni];
            float2 bb = *(const float2*)(bff + col);
            float2 x0 = *(const float2*)(xp + (size_t)r0 * 512 + col);
            float2 x1 = *(const float2*)(xp + (size_t)r1 * 512 + col);
            float2 o0 = make_float2(c.x + bb.x + x0.x, c.y + bb.y + x0.y);
            float2 o1 = make_float2(c.z + bb.x + x1.x, c.w + bb.y + x1.y);
            *(float2*)(out + (size_t)r0 * 512 + col) = o0;
            *(float2*)(out + (size_t)r1 * 512 + col) = o1;
        }
    }
}

// ---------------------------------------------------------------------------
// Repack K and V into bf16 m16n8k16 B-fragment layout.
// K (kind 0): fg=(nblk,kc2): u32 r -> {K[nblk*8+g][d0], K[..][d0+1]},
//             d0 = (kc2*2+(r>>1))*16 + (r&1)*8 + 2*tg
// V (kind 1): fg=(dblk,kc2): u32 r -> {V[k0][dblk*8+g], V[k0+1][..]},
//             k0 = (kc2*2+(r>>1))*16 + (r&1)*8 + 2*tg
// ---------------------------------------------------------------------------
__global__ __launch_bounds__(256) void repack_kv_kernel()
{
    const int kt = blockIdx.x, bh = blockIdx.y, kind = blockIdx.z;
    __shared__ float ts[64][68];
    const float* src = (kind ? g_v : g_k) + ((size_t)bh * 2048 + kt * 64) * 64;
    const int tid = threadIdx.x;
#pragma unroll
    for (int r = 0; r < 4; r++) {
        int e = tid + r * 256;
        int row = e >> 4, c4 = (e & 15) * 4;
        float4 v = *(const float4*)(src + row * 64 + c4);
        ts[row][c4 + 0] = v.x; ts[row][c4 + 1] = v.y;
        ts[row][c4 + 2] = v.z; ts[row][c4 + 3] = v.w;
    }
    __syncthreads();
    const int w = tid >> 5, lane = tid & 31, g = lane >> 2, tg = lane & 3;
    uint4* dst4 = (uint4*)((kind ? g_vsw : g_ksw) + ((size_t)bh * 32 + kt) * 2048);
#pragma unroll
    for (int i = 0; i < 2; i++) {
        int fg = w + i * 8;           // 0..15
        int blk = fg >> 1, kc2 = fg & 1;
        uint4 o;
        uint32_t* op = (uint32_t*)&o;
#pragma unroll
        for (int r = 0; r < 4; r++) {
            int e0 = (kc2 * 2 + (r >> 1)) * 16 + (r & 1) * 8 + 2 * tg;
            float v0, v1;
            if (kind == 0) { v0 = ts[blk * 8 + g][e0];  v1 = ts[blk * 8 + g][e0 + 1]; }
            else           { v0 = ts[e0][blk * 8 + g];  v1 = ts[e0 + 1][blk * 8 + g]; }
            op[r] = pkbf(v0, v1);
        }
        dst4[fg * 32 + lane] = o;
    }
}

// ---------------------------------------------------------------------------
// Flash attention, bf16 m16n8k16 mma. CTA = 4 warps x 32 q-rows = 128 rows.
// P re-fragmentation is a pure register pack (no shuffles).
// ---------------------------------------------------------------------------
__global__ __launch_bounds__(128, 2) void attn_mma_kernel(
    const float* __restrict__ bias, const float* __restrict__ gamma_f)
{
    extern __shared__ __align__(16) uint32_t smu[];   // 2 stages x 4096 u32
    const int qt = blockIdx.x, h = blockIdx.y, b = blockIdx.z;
    const int bh = b * 8 + h;
    const int tid = threadIdx.x, wid = tid >> 5, lane = tid & 31;
    const int g = lane >> 2, tg = lane & 3;
    const float gamma = __ldg(gamma_f + h);

    // Q fragments (bf16 m16k16 A-layout), both m16 halves, once per CTA
    uint32_t Qh0[4][4], Qh1[4][4];
    {
        const float* qp = g_q + ((size_t)bh * 2048 + qt * 128 + wid * 32) * 64;
#pragma unroll
        for (int c = 0; c < 4; c++) {
            int d0 = c * 16 + 2 * tg;
            int d1 = d0 + 8;
            Qh0[c][0] = pkbf(qp[g * 64 + d0],        qp[g * 64 + d0 + 1]);
            Qh0[c][1] = pkbf(qp[(g + 8) * 64 + d0],  qp[(g + 8) * 64 + d0 + 1]);
            Qh0[c][2] = pkbf(qp[g * 64 + d1],        qp[g * 64 + d1 + 1]);
            Qh0[c][3] = pkbf(qp[(g + 8) * 64 + d1],  qp[(g + 8) * 64 + d1 + 1]);
            Qh1[c][0] = pkbf(qp[(g + 16) * 64 + d0], qp[(g + 16) * 64 + d0 + 1]);
            Qh1[c][1] = pkbf(qp[(g + 24) * 64 + d0], qp[(g + 24) * 64 + d0 + 1]);
            Qh1[c][2] = pkbf(qp[(g + 16) * 64 + d1], qp[(g + 16) * 64 + d1 + 1]);
            Qh1[c][3] = pkbf(qp[(g + 24) * 64 + d1], qp[(g + 24) * 64 + d1 + 1]);
        }
    }

    float4 Oc0[8], Oc1[8];
#pragma unroll
    for (int j = 0; j < 8; j++) {
        Oc0[j] = make_float4(0.f, 0.f, 0.f, 0.f);
        Oc1[j] = make_float4(0.f, 0.f, 0.f, 0.f);
    }
    float mr[4] = {-1e30f, -1e30f, -1e30f, -1e30f};
    float lr[4] = {0.f, 0.f, 0.f, 0.f};

    const uint32_t* ksrc = g_ksw + (size_t)bh * 32 * 2048;
    const uint32_t* vsrc = g_vsw + (size_t)bh * 32 * 2048;
    const float* bp = bias + ((size_t)b * 2048 + qt * 128 + wid * 32) * 2048;
    const unsigned char* mp = g_mask + b * 2048;

    // prefetch tile 0: stage = 2048 u32 K + 2048 u32 V; 128 thr x 4 uint4 each
    {
#pragma unroll
        for (int i = 0; i < 4; i++) {
            cpasync16(smu + (tid + i * 128) * 4, ksrc + (size_t)(tid + i * 128) * 4);
            cpasync16(smu + 2048 + (tid + i * 128) * 4, vsrc + (size_t)(tid + i * 128) * 4);
        }
        cp_commit();
    }

    for (int kt = 0; kt < 32; kt++) {
        __syncthreads();
        if (kt + 1 < 32) {
            uint32_t* dstb = smu + ((kt + 1) & 1) * 4096;
            const uint32_t* kg = ksrc + (size_t)(kt + 1) * 2048;
            const uint32_t* vg = vsrc + (size_t)(kt + 1) * 2048;
#pragma unroll
            for (int i = 0; i < 4; i++) {
                cpasync16(dstb + (tid + i * 128) * 4, kg + (size_t)(tid + i * 128) * 4);
                cpasync16(dstb + 2048 + (tid + i * 128) * 4, vg + (size_t)(tid + i * 128) * 4);
            }
            cp_commit();
            cp_wait<1>();
        } else {
            cp_wait<0>();
        }
        __syncthreads();

        const uint4* Kf4 = (const uint4*)(smu + (kt & 1) * 4096);
        const uint4* Vf4 = Kf4 + 512;
        const float* bt = bp + kt * 64;

        // S = Q K^T, both m16 halves; bias/mask per n8 block j
        float4 Sc0[8], Sc1[8];
#pragma unroll
        for (int j = 0; j < 8; j++) {
            uchar2 mk = *(const uchar2*)(mp + kt * 64 + j * 8 + 2 * tg);
            float2 b0 = *(const float2*)(bt + (size_t)g * 2048 + j * 8 + 2 * tg);
            float2 b1 = *(const float2*)(bt + (size_t)(g + 8) * 2048 + j * 8 + 2 * tg);
            float2 b2 = *(const float2*)(bt + (size_t)(g + 16) * 2048 + j * 8 + 2 * tg);
            float2 b3 = *(const float2*)(bt + (size_t)(g + 24) * 2048 + j * 8 + 2 * tg);
            uint4 kA = Kf4[(j * 2 + 0) * 32 + lane];
            uint4 kB = Kf4[(j * 2 + 1) * 32 + lane];
            float4 c0 = make_float4(0.f, 0.f, 0.f, 0.f);
            float4 c1 = make_float4(0.f, 0.f, 0.f, 0.f);
            mma16(c0, Qh0[0], kA.x, kA.y);
            mma16(c0, Qh0[1], kA.z, kA.w);
            mma16(c0, Qh0[2], kB.x, kB.y);
            mma16(c0, Qh0[3], kB.z, kB.w);
            mma16(c1, Qh1[0], kA.x, kA.y);
            mma16(c1, Qh1[1], kA.z, kA.w);
            mma16(c1, Qh1[2], kB.x, kB.y);
            mma16(c1, Qh1[3], kB.z, kB.w);
            c0.x = mk.x ? -1e9f : fmaf(gamma, b0.x, c0.x);
            c0.y = mk.y ? -1e9f : fmaf(gamma, b0.y, c0.y);
            c0.z = mk.x ? -1e9f : fmaf(gamma, b1.x, c0.z);
            c0.w = mk.y ? -1e9f : fmaf(gamma, b1.y, c0.w);
            c1.x = mk.x ? -1e9f : fmaf(gamma, b2.x, c1.x);
            c1.y = mk.y ? -1e9f : fmaf(gamma, b2.y, c1.y);
            c1.z = mk.x ? -1e9f : fmaf(gamma, b3.x, c1.z);
            c1.w = mk.y ? -1e9f : fmaf(gamma, b3.y, c1.w);
            Sc0[j] = c0;
            Sc1[j] = c1;
        }

        // online softmax over 4 row-groups (quad lanes share rows)
        float tm[4] = {-1e30f, -1e30f, -1e30f, -1e30f};
#pragma unroll
        for (int j = 0; j < 8; j++) {
            tm[0] = fmaxf(tm[0], fmaxf(Sc0[j].x, Sc0[j].y));
            tm[1] = fmaxf(tm[1], fmaxf(Sc0[j].z, Sc0[j].w));
            tm[2] = fmaxf(tm[2], fmaxf(Sc1[j].x, Sc1[j].y));
            tm[3] = fmaxf(tm[3], fmaxf(Sc1[j].z, Sc1[j].w));
        }
        float sc[4];
#pragma unroll
        for (int r = 0; r < 4; r++) {
            tm[r] = fmaxf(tm[r], __shfl_xor_sync(0xffffffffu, tm[r], 1));
            tm[r] = fmaxf(tm[r], __shfl_xor_sync(0xffffffffu, tm[r], 2));
            float mn = fmaxf(mr[r], tm[r]);
            sc[r] = __expf(mr[r] - mn);
            mr[r] = mn;
        }
        float rs[4] = {0.f, 0.f, 0.f, 0.f};
#pragma unroll
        for (int j = 0; j < 8; j++) {
            Sc0[j].x = __expf(Sc0[j].x - mr[0]);
            Sc0[j].y = __expf(Sc0[j].y - mr[0]);
            Sc0[j].z = __expf(Sc0[j].z - mr[1]);
            Sc0[j].w = __expf(Sc0[j].w - mr[1]);
            Sc1[j].x = __expf(Sc1[j].x - mr[2]);
            Sc1[j].y = __expf(Sc1[j].y - mr[2]);
            Sc1[j].z = __expf(Sc1[j].z - mr[3]);
            Sc1[j].w = __expf(Sc1[j].w - mr[3]);
            rs[0] += Sc0[j].x + Sc0[j].y;
            rs[1] += Sc0[j].z + Sc0[j].w;
            rs[2] += Sc1[j].x + Sc1[j].y;
            rs[3] += Sc1[j].z + Sc1[j].w;
        }
#pragma unroll
        for (int r = 0; r < 4; r++) {
            rs[r] += __shfl_xor_sync(0xffffffffu, rs[r], 1);
            rs[r] += __shfl_xor_sync(0xffffffffu, rs[r], 2);
            lr[r] = lr[r] * sc[r] + rs[r];
        }
#pragma unroll
        for (int j = 0; j < 8; j++) {
            Oc0[j].x *= sc[0]; Oc0[j].y *= sc[0];
            Oc0[j].z *= sc[1]; Oc0[j].w *= sc[1];
            Oc1[j].x *= sc[2]; Oc1[j].y *= sc[2];
            Oc1[j].z *= sc[3]; Oc1[j].w *= sc[3];
        }

        // P: C-layout -> bf16 A-frags by direct register pack (NO shuffles)
        uint32_t Pa0[4][4], Pa1[4][4];
#pragma unroll
        for (int c = 0; c < 4; c++) {
            Pa0[c][0] = pkbf(Sc0[2*c].x,     Sc0[2*c].y);
            Pa0[c][1] = pkbf(Sc0[2*c].z,     Sc0[2*c].w);
            Pa0[c][2] = pkbf(Sc0[2*c + 1].x, Sc0[2*c + 1].y);
            Pa0[c][3] = pkbf(Sc0[2*c + 1].z, Sc0[2*c + 1].w);
            Pa1[c][0] = pkbf(Sc1[2*c].x,     Sc1[2*c].y);
            Pa1[c][1] = pkbf(Sc1[2*c].z,     Sc1[2*c].w);
            Pa1[c][2] = pkbf(Sc1[2*c + 1].x, Sc1[2*c + 1].y);
            Pa1[c][3] = pkbf(Sc1[2*c + 1].z, Sc1[2*c + 1].w);
        }

        // O += P V
#pragma unroll
        for (int j = 0; j < 8; j++) {
            uint4 vA = Vf4[(j * 2 + 0) * 32 + lane];
            uint4 vB = Vf4[(j * 2 + 1) * 32 + lane];
            mma16(Oc0[j], Pa0[0], vA.x, vA.y);
            mma16(Oc0[j], Pa0[1], vA.z, vA.w);
            mma16(Oc0[j], Pa0[2], vB.x, vB.y);
            mma16(Oc0[j], Pa0[3], vB.z, vB.w);
            mma16(Oc1[j], Pa1[0], vA.x, vA.y);
            mma16(Oc1[j], Pa1[1], vA.z, vA.w);
            mma16(Oc1[j], Pa1[2], vB.x, vB.y);
            mma16(Oc1[j], Pa1[3], vB.z, vB.w);
        }
    }

    const float i0 = 1.f / lr[0], i1 = 1.f / lr[1];
    const float i2 = 1.f / lr[2], i3 = 1.f / lr[3];
    float* op = g_att + ((size_t)b * 2048 + qt * 128 + wid * 32) * 512 + h * 64;
#pragma unroll
    for (int j = 0; j < 8; j++) {
        int col = j * 8 + 2 * tg;
        *(float2*)(op + (size_t)g * 512 + col) =
            make_float2(Oc0[j].x * i0, Oc0[j].y * i0);
        *(float2*)(op + (size_t)(g + 8) * 512 + col) =
            make_float2(Oc0[j].z * i1, Oc0[j].w * i1);
        *(float2*)(op + (size_t)(g + 16) * 512 + col) =
            make_float2(Oc1[j].x * i2, Oc1[j].y * i2);
        *(float2*)(op + (size_t)(g + 24) * 512 + col) =
            make_float2(Oc1[j].z * i3, Oc1[j].w * i3);
    }
}

// ---------------------------------------------------------------------------
// LayerNorm in-place on d_out
// ---------------------------------------------------------------------------
__global__ __launch_bounds__(128) void ln_kernel(
    float* __restrict__ y, const float* __restrict__ g,
    const float* __restrict__ be)
{
    const int row = blockIdx.x;
    const int tid = threadIdx.x;
    float4 v = *(const float4*)(y + (size_t)row * 512 + tid * 4);
    float s = (v.x + v.y) + (v.z + v.w);
    float q = (v.x * v.x + v.y * v.y) + (v.z * v.z + v.w * v.w);
#pragma unroll
    for (int msk = 16; msk; msk >>= 1) {
        s += __shfl_xor_sync(0xffffffffu, s, msk);
        q += __shfl_xor_sync(0xffffffffu, q, msk);
    }
    __shared__ float ss[4], sq[4];
    const int w = tid >> 5;
    if ((tid & 31) == 0) { ss[w] = s; sq[w] = q; }
    __syncthreads();
    s = (ss[0] + ss[1]) + (ss[2] + ss[3]);
    q = (sq[0] + sq[1]) + (sq[2] + sq[3]);
    const float mu = s * (1.0f / 512.0f);
    const float var = q * (1.0f / 512.0f) - mu * mu;
    const float rs = rsqrtf(var + 1e-5f);
    float4 gg = *(const float4*)(g + tid * 4);
    float4 bb = *(const float4*)(be + tid * 4);
    float4 r;
    r.x = (v.x - mu) * rs * gg.x + bb.x;
    r.y = (v.y - mu) * rs * gg.y + bb.y;
    r.z = (v.z - mu) * rs * gg.z + bb.z;
    r.w = (v.w - mu) * rs * gg.w + bb.w;
    *(float4*)(y + (size_t)row * 512 + tid * 4) = r;
}

// ---------------------------------------------------------------------------
extern "C" void kernel_launch(void* const* d_in, const int* in_sizes, int n_in,
                              void* d_out, int out_size)
{
    const float* xp      = (const float*)d_in[0];
    const float* xpcre   = (const float*)d_in[1];
    const float* bias    = (const float*)d_in[2];
    const void*  mask    = d_in[3];
    const float* Wq      = (const float*)d_in[4];
    const float* Wkv     = (const float*)d_in[5];
    const float* Wff     = (const float*)d_in[6];
    const float* bff     = (const float*)d_in[7];
    const float* gamma_f = (const float*)d_in[8];
    const float* ln_g    = (const float*)d_in[9];
    const float* ln_b    = (const float*)d_in[10];
    float* out = (float*)d_out;

    const int attn_smem = 2 * 4096 * 4;     // 32768 B
    const int gemm_smem = 2 * STG_F * 4;    // 37888 B
    cudaFuncSetAttribute(attn_mma_kernel,
                         cudaFuncAttributeMaxDynamicSharedMemorySize, attn_smem);
    cudaFuncSetAttribute(proj_tc_kernel,
                         cudaFuncAttributeMaxDynamicSharedMemorySize, gemm_smem);
    cudaFuncSetAttribute(ff_tc_kernel,
                         cudaFuncAttributeMaxDynamicSharedMemorySize, gemm_smem);

    mask_norm_kernel<<<1, 256>>>(mask);

    dim3 pg(12, 128);
    proj_tc_kernel<<<pg, 256, gemm_smem>>>(xp, xpcre, Wq, Wkv);

    dim3 rg(32, 64, 2);
    repack_kv_kernel<<<rg, 256>>>();

    dim3 ag(16, 8, 8);   // (qtile128, h, b), 4 warps x 32 rows
    attn_mma_kernel<<<ag, 128, attn_smem>>>(bias, gamma_f);

    dim3 fg(4, 128);
    ff_tc_kernel<<<fg, 256, gemm_smem>>>(Wff, bff, xp, out);

    ln_kernel<<<BB * SS, 128>>>(out, ln_g, ln_b);
}

// round 15
// speedup vs baseline: 5.1829x; 1.1431x over previous
#include <cuda_runtime.h>
#include <cuda_bf16.h>
#include <cstdint>

#define BB 8
#define SS 2048
#define DE 512
#define HH 8
#define DH 64

// Scratch (allocation-free: device globals)
__device__ __align__(16) uint32_t g_xh[BB*SS*256];    // x_p   bf16x2 [m][256]
__device__ __align__(16) uint32_t g_xch[BB*SS*256];   // x_pcre bf16x2
__device__ __align__(16) uint32_t g_wqt[512*256];     // Wq^T  bf16x2 [n][k/2]
__device__ __align__(16) uint32_t g_wkvt[1024*256];   // Wkv^T bf16x2 [n][k/2]
__device__ __align__(16) uint32_t g_qh[BB*HH*SS*32];  // q bf16x2 [bh][s][d/2] (pre-scaled 1/8)
__device__ __align__(16) uint32_t g_kh[BB*HH*SS*32];  // k bf16x2
__device__ __align__(16) uint32_t g_vh[BB*HH*SS*32];  // v bf16x2
__device__ float g_att[BB*SS*DE];                     // [b][s][h*64+d] fp32
__device__ unsigned char g_mask[BB*SS];
// bf16 m16n8k16 B-fragment layout per 64x64 tile:
//   [fg(16)=(blk8,kc2)][lane(32)][4 u32]
__device__ __align__(16) uint32_t g_ksw[BB*HH*32*2048];
__device__ __align__(16) uint32_t g_vsw[BB*HH*32*2048];

// ---------------------------------------------------------------------------
// small helpers
// ---------------------------------------------------------------------------
__device__ __forceinline__ uint32_t f2tf32(float f) {
    uint32_t u;
    asm("cvt.rna.tf32.f32 %0, %1;" : "=r"(u) : "f"(f));
    return u;
}
// pack two floats to bf16x2: lo = a (element 0), hi = b (element 1)
__device__ __forceinline__ uint32_t pkbf(float lo, float hi) {
    uint32_t r;
    asm("cvt.rn.bf16x2.f32 %0, %1, %2;" : "=r"(r) : "f"(hi), "f"(lo));
    return r;
}
__device__ __forceinline__ void mma8(float4& c, const uint32_t a[4],
                                     uint32_t b0, uint32_t b1) {
    asm volatile(
        "mma.sync.aligned.m16n8k8.row.col.f32.tf32.tf32.f32 "
        "{%0,%1,%2,%3},{%4,%5,%6,%7},{%8,%9},{%0,%1,%2,%3};"
        : "+f"(c.x), "+f"(c.y), "+f"(c.z), "+f"(c.w)
        : "r"(a[0]), "r"(a[1]), "r"(a[2]), "r"(a[3]), "r"(b0), "r"(b1));
}
__device__ __forceinline__ void mma16(float4& c, const uint32_t a[4],
                                      uint32_t b0, uint32_t b1) {
    asm volatile(
        "mma.sync.aligned.m16n8k16.row.col.f32.bf16.bf16.f32 "
        "{%0,%1,%2,%3},{%4,%5,%6,%7},{%8,%9},{%0,%1,%2,%3};"
        : "+f"(c.x), "+f"(c.y), "+f"(c.z), "+f"(c.w)
        : "r"(a[0]), "r"(a[1]), "r"(a[2]), "r"(a[3]), "r"(b0), "r"(b1));
}
__device__ __forceinline__ void cpasync16(void* s, const void* g) {
    uint32_t sa = (uint32_t)__cvta_generic_to_shared(s);
    asm volatile("cp.async.cg.shared.global [%0], [%1], 16;" :: "r"(sa), "l"(g));
}
__device__ __forceinline__ void cp_commit() {
    asm volatile("cp.async.commit_group;" ::: "memory");
}
template <int N>
__device__ __forceinline__ void cp_wait() {
    asm volatile("cp.async.wait_group %0;" :: "n"(N) : "memory");
}

// ---------------------------------------------------------------------------
// Mask dtype probe + normalize
// ---------------------------------------------------------------------------
__global__ void mask_norm_kernel(const void* __restrict__ mraw)
{
    __shared__ int s_nz, s_3f;
    const int tid = threadIdx.x;
    if (tid == 0) { s_nz = 0; s_3f = 0; }
    __syncthreads();
    const unsigned char* u8 = (const unsigned char*)mraw;
    int nz = 0, c3 = 0;
    for (int i = tid; i < BB*SS; i += 256) {
        unsigned char c = u8[i];
        nz += (c != 0);
        c3 += (c == 0x3F);
    }
    atomicAdd(&s_nz, nz);
    atomicAdd(&s_3f, c3);
    __syncthreads();
    int mode = (s_3f > 100) ? 2 : ((s_nz > 1000) ? 0 : 1);
    for (int i = tid; i < BB*SS; i += 256) {
        unsigned char m;
        if (mode == 2)      m = (((const float*)mraw)[i] != 0.0f);
        else if (mode == 1) m = (((const int*)mraw)[i] != 0);
        else                m = (u8[i] != 0);
        g_mask[i] = m;
    }
}

// ---------------------------------------------------------------------------
// Prep: convert x_p / x_pcre to bf16x2
// ---------------------------------------------------------------------------
__global__ __launch_bounds__(256) void conv_x_kernel(
    const float* __restrict__ xp, const float* __restrict__ xc)
{
    const int idx = blockIdx.x * 256 + threadIdx.x;   // < BB*SS*256
    float2 a = ((const float2*)xp)[idx];
    float2 b = ((const float2*)xc)[idx];
    g_xh[idx]  = pkbf(a.x, a.y);
    g_xch[idx] = pkbf(b.x, b.y);
}

// ---------------------------------------------------------------------------
// Prep: transpose W (fp32 [k][n]) -> bf16x2 [n][k/2]
// z=0: Wq (512x512), z=1: Wkv (512x1024)
// ---------------------------------------------------------------------------
__global__ __launch_bounds__(256) void conv_w_kernel(
    const float* __restrict__ Wq, const float* __restrict__ Wkv)
{
    const int z = blockIdx.z;
    const float* W = z ? Wkv : Wq;
    const int ldn = z ? 1024 : 512;
    uint32_t* out = z ? g_wkvt : g_wqt;
    const int n0 = blockIdx.x * 32, k0 = blockIdx.y * 32;
    if (n0 >= ldn) return;
    __shared__ float ts[32][33];
    const int tx = threadIdx.x & 31, ty = threadIdx.x >> 5;
#pragma unroll
    for (int r = 0; r < 4; r++)
        ts[ty + r * 8][tx] = W[(size_t)(k0 + ty + r * 8) * ldn + n0 + tx];
    __syncthreads();
#pragma unroll
    for (int i = 0; i < 2; i++) {
        int e = threadIdx.x + i * 256;
        int n = e >> 4, j = e & 15;
        out[(size_t)(n0 + n) * 256 + (k0 >> 1) + j] = pkbf(ts[2*j][n], ts[2*j+1][n]);
    }
}

// ---------------------------------------------------------------------------
// QKV projection, bf16 m16n8k16. CTA 128x128, k32/stage, double-buffered.
// smem rows padded to 20 u32 -> bank(20g+tg) is a 32-permutation: conflict-free.
// grid (12 nt, 128 mt): nt 0-3 q, 4-7 k, 8-11 v.
// ---------------------------------------------------------------------------
#define PSTG 5120   // u32 per stage: A 128*20 + B 128*20

__global__ __launch_bounds__(256) void proj_bf_kernel()
{
    extern __shared__ __align__(16) uint32_t su[];
    const int nt = blockIdx.x, mt = blockIdx.y;
    const int grp = nt >> 2;
    const int ncol0 = (nt & 3) * 128;
    const uint32_t* __restrict__ A  = (grp == 0) ? g_xh : g_xch;
    const uint32_t* __restrict__ Wt = (grp == 0) ? g_wqt : g_wkvt;
    const int wr0 = (grp == 2) ? (512 + ncol0) : ncol0;
    uint32_t* dst = (grp == 0) ? g_qh : ((grp == 1) ? g_kh : g_vh);
    const float osc = (grp == 0) ? 0.125f : 1.0f;

    const int tid = threadIdx.x, wid = tid >> 5, lane = tid & 31;
    const int g = lane >> 2, tg = lane & 3;
    const int wm = wid >> 2, wn = wid & 3;
    const int m0 = mt * 128;

    float4 C[4][4];
#pragma unroll
    for (int mi = 0; mi < 4; mi++)
#pragma unroll
        for (int ni = 0; ni < 4; ni++) C[mi][ni] = make_float4(0.f,0.f,0.f,0.f);

    // stage loader: k0u = stage*16 (u32 units of k)
    auto stage_load = [&](uint32_t* S, int k0u) {
        uint32_t* Sb = S + 2560;
#pragma unroll
        for (int i = 0; i < 2; i++) {
            int e = tid + i * 256;
            int row = e >> 2, cq = (e & 3) * 4;
            cpasync16(S + row * 20 + cq, A + (size_t)(m0 + row) * 256 + k0u + cq);
            cpasync16(Sb + row * 20 + cq, Wt + (size_t)(wr0 + row) * 256 + k0u + cq);
        }
    };

    stage_load(su, 0);
    cp_commit();

    for (int kt = 0; kt < 16; kt++) {
        __syncthreads();
        if (kt + 1 < 16) {
            stage_load(su + ((kt + 1) & 1) * PSTG, (kt + 1) * 16);
            cp_commit();
            cp_wait<1>();
        } else {
            cp_wait<0>();
        }
        __syncthreads();
        const uint32_t* Sa = su + (kt & 1) * PSTG;
        const uint32_t* Sb = Sa + 2560;
#pragma unroll
        for (int ks = 0; ks < 2; ks++) {
            const int base = ks * 8;
            uint32_t a[4][4];
#pragma unroll
            for (int mi = 0; mi < 4; mi++) {
                const uint32_t* ap = Sa + (wm * 64 + mi * 16) * 20 + base + tg;
                a[mi][0] = ap[g * 20];
                a[mi][1] = ap[(g + 8) * 20];
                a[mi][2] = ap[g * 20 + 4];
                a[mi][3] = ap[(g + 8) * 20 + 4];
            }
            uint32_t bf[4][2];
#pragma unroll
            for (int ni = 0; ni < 4; ni++) {
                const uint32_t* bp = Sb + (wn * 32 + ni * 8 + g) * 20 + base + tg;
                bf[ni][0] = bp[0];
                bf[ni][1] = bp[4];
            }
#pragma unroll
            for (int mi = 0; mi < 4; mi++)
#pragma unroll
                for (int ni = 0; ni < 4; ni++)
                    mma16(C[mi][ni], a[mi], bf[ni][0], bf[ni][1]);
        }
    }

    // epilogue: pack fp32 accum -> bf16x2, strided per-head store
#pragma unroll
    for (int mi = 0; mi < 4; mi++) {
        int r0 = m0 + wm * 64 + mi * 16 + g;
        int r1 = r0 + 8;
        int b0 = r0 >> 11, s0 = r0 & 2047;
        int b1 = r1 >> 11, s1 = r1 & 2047;
#pragma unroll
        for (int ni = 0; ni < 4; ni++) {
            int col = ncol0 + wn * 32 + ni * 8 + 2 * tg;
            int h = col >> 6, d = col & 63;
            float4 c = C[mi][ni];
            dst[((size_t)(b0 * 8 + h) * 2048 + s0) * 32 + (d >> 1)] =
                pkbf(c.x * osc, c.y * osc);
            dst[((size_t)(b1 * 8 + h) * 2048 + s1) * 32 + (d >> 1)] =
                pkbf(c.z * osc, c.w * osc);
        }
    }
}

// ===========================================================================
// tf32 GEMM core (ff only): CTA 128x128, K-step 16, double-buffered.
// ===========================================================================
#define STG_F (128*20 + 16*136)   // 4736 floats per stage

struct Frag16 {
    float4 c[4][4];
};

__device__ __forceinline__ void gemm_stage_load(
    float* Sa, const float* __restrict__ A, const float* __restrict__ W,
    int m0, int k0, int ldw, int wc0, int tid)
{
    float* Sb = Sa + 128*20;
#pragma unroll
    for (int i = 0; i < 2; i++) {
        int e = tid + i * 256;
        int row = e >> 2, kq = (e & 3) * 4;
        cpasync16(Sa + row * 20 + kq, A + (size_t)(m0 + row) * 512 + k0 + kq);
    }
#pragma unroll
    for (int i = 0; i < 2; i++) {
        int e = tid + i * 256;
        int row = e >> 5, nq = (e & 31) * 4;
        cpasync16(Sb + row * 136 + nq, W + (size_t)(k0 + row) * ldw + wc0 + nq);
    }
}

__device__ __forceinline__ void gemm_compute_stage(
    Frag16& F, const float* Sa, int wm, int wn, int g, int tg)
{
    const float* Sb = Sa + 128*20;
#pragma unroll
    for (int ks = 0; ks < 2; ks++) {
        uint32_t a[4][4];
#pragma unroll
        for (int mi = 0; mi < 4; mi++) {
            const float* ap = Sa + (wm * 64 + mi * 16) * 20 + ks * 8 + tg;
            a[mi][0] = f2tf32(ap[g * 20]);
            a[mi][1] = f2tf32(ap[(g + 8) * 20]);
            a[mi][2] = f2tf32(ap[g * 20 + 4]);
            a[mi][3] = f2tf32(ap[(g + 8) * 20 + 4]);
        }
        uint32_t bf[4][2];
#pragma unroll
        for (int ni = 0; ni < 4; ni++) {
            const float* bp = Sb + (ks * 8 + tg) * 136 + wn * 32 + ni * 8 + g;
            bf[ni][0] = f2tf32(bp[0]);
            bf[ni][1] = f2tf32(bp[4 * 136]);
        }
#pragma unroll
        for (int mi = 0; mi < 4; mi++)
#pragma unroll
            for (int ni = 0; ni < 4; ni++)
                mma8(F.c[mi][ni], a[mi], bf[ni][0], bf[ni][1]);
    }
}

// ---------------------------------------------------------------------------
// FF, tf32 mma: y = x_p + att @ Wff + bff. grid (4 nt, 128 mt).
// ---------------------------------------------------------------------------
__global__ __launch_bounds__(256) void ff_tc_kernel(
    const float* __restrict__ Wff, const float* __restrict__ bff,
    const float* __restrict__ xp, float* __restrict__ out)
{
    extern __shared__ __align__(16) float sm[];
    const int nt = blockIdx.x, mt = blockIdx.y;
    const int ncol0 = nt * 128;
    const int tid = threadIdx.x, wid = tid >> 5, lane = tid & 31;
    const int g = lane >> 2, tg = lane & 3;
    const int wm = wid >> 2, wn = wid & 3;
    const int m0 = mt * 128;

    Frag16 F;
#pragma unroll
    for (int mi = 0; mi < 4; mi++)
#pragma unroll
        for (int ni = 0; ni < 4; ni++) F.c[mi][ni] = make_float4(0.f,0.f,0.f,0.f);

    gemm_stage_load(sm, g_att, Wff, m0, 0, 512, ncol0, tid);
    cp_commit();

    for (int kt = 0; kt < 32; kt++) {
        __syncthreads();
        if (kt + 1 < 32) {
            gemm_stage_load(sm + ((kt + 1) & 1) * STG_F, g_att, Wff, m0,
                            (kt + 1) * 16, 512, ncol0, tid);
            cp_commit();
            cp_wait<1>();
        } else {
            cp_wait<0>();
        }
        __syncthreads();
        gemm_compute_stage(F, sm + (kt & 1) * STG_F, wm, wn, g, tg);
    }

#pragma unroll
    for (int mi = 0; mi < 4; mi++) {
        int r0 = m0 + wm * 64 + mi * 16 + g;
        int r1 = r0 + 8;
#pragma unroll
        for (int ni = 0; ni < 4; ni++) {
            int col = ncol0 + wn * 32 + ni * 8 + 2 * tg;
            float4 c = F.c[mi][ni];
            float2 bb = *(const float2*)(bff + col);
            float2 x0 = *(const float2*)(xp + (size_t)r0 * 512 + col);
            float2 x1 = *(const float2*)(xp + (size_t)r1 * 512 + col);
            float2 o0 = make_float2(c.x + bb.x + x0.x, c.y + bb.y + x0.y);
            float2 o1 = make_float2(c.z + bb.x + x1.x, c.w + bb.y + x1.y);
            *(float2*)(out + (size_t)r0 * 512 + col) = o0;
            *(float2*)(out + (size_t)r1 * 512 + col) = o1;
        }
    }
}

// ---------------------------------------------------------------------------
// Repack K and V (bf16x2 in) into m16n8k16 B-fragment layout. No cvt.
// ---------------------------------------------------------------------------
__global__ __launch_bounds__(256) void repack_kv_kernel()
{
    const int kt = blockIdx.x, bh = blockIdx.y, kind = blockIdx.z;
    __shared__ uint32_t ts[64][33];
    const uint32_t* src = (kind ? g_vh : g_kh) + ((size_t)bh * 2048 + kt * 64) * 32;
    const int tid = threadIdx.x;
#pragma unroll
    for (int i = 0; i < 2; i++) {
        int e = tid + i * 256;
        int row = e >> 3, c4 = (e & 7) * 4;
        uint4 v = *(const uint4*)(src + row * 32 + c4);
        ts[row][c4 + 0] = v.x; ts[row][c4 + 1] = v.y;
        ts[row][c4 + 2] = v.z; ts[row][c4 + 3] = v.w;
    }
    __syncthreads();
    const int w = tid >> 5, lane = tid & 31, g = lane >> 2, tg = lane & 3;
    uint4* dst4 = (uint4*)((kind ? g_vsw : g_ksw) + ((size_t)bh * 32 + kt) * 2048);
#pragma unroll
    for (int i = 0; i < 2; i++) {
        int fg = w + i * 8;           // 0..15
        int blk = fg >> 1, kc2 = fg & 1;
        uint4 o;
        uint32_t* op = (uint32_t*)&o;
#pragma unroll
        for (int r = 0; r < 4; r++) {
            if (kind == 0) {
                // {K[blk*8+g][d0], K[..][d0+1]} with d0 even -> one u32
                int cu = (kc2 * 2 + (r >> 1)) * 8 + (r & 1) * 4 + tg;
                op[r] = ts[blk * 8 + g][cu];
            } else {
                // {V[e0][d], V[e0+1][d]}: halves of two row-adjacent u32
                int e0 = (kc2 * 2 + (r >> 1)) * 16 + (r & 1) * 8 + 2 * tg;
                int d  = blk * 8 + g;
                uint32_t x0 = ts[e0][d >> 1];
                uint32_t x1 = ts[e0 + 1][d >> 1];
                op[r] = __byte_perm(x0, x1, (d & 1) ? 0x7632 : 0x5410);
            }
        }
        dst4[fg * 32 + lane] = o;
    }
}

// ---------------------------------------------------------------------------
// Flash attention, bf16 m16n8k16 mma. CTA = 4 warps x 32 q-rows = 128 rows.
// Q frags load as raw u32 (q already bf16x2). P repack is register packs.
// ---------------------------------------------------------------------------
__global__ __launch_bounds__(128, 2) void attn_mma_kernel(
    const float* __restrict__ bias, const float* __restrict__ gamma_f)
{
    extern __shared__ __align__(16) uint32_t smu[];   // 2 stages x 4096 u32
    const int qt = blockIdx.x, h = blockIdx.y, b = blockIdx.z;
    const int bh = b * 8 + h;
    const int tid = threadIdx.x, wid = tid >> 5, lane = tid & 31;
    const int g = lane >> 2, tg = lane & 3;
    const float gamma = __ldg(gamma_f + h);

    // Q fragments: direct u32 loads (bf16x2, d-pairs contiguous)
    uint32_t Qh0[4][4], Qh1[4][4];
    {
        const uint32_t* qp = g_qh + ((size_t)bh * 2048 + qt * 128 + wid * 32) * 32;
#pragma unroll
        for (int c = 0; c < 4; c++) {
            int cu = c * 8 + tg;
            Qh0[c][0] = qp[g * 32 + cu];
            Qh0[c][1] = qp[(g + 8) * 32 + cu];
            Qh0[c][2] = qp[g * 32 + cu + 4];
            Qh0[c][3] = qp[(g + 8) * 32 + cu + 4];
            Qh1[c][0] = qp[(g + 16) * 32 + cu];
            Qh1[c][1] = qp[(g + 24) * 32 + cu];
            Qh1[c][2] = qp[(g + 16) * 32 + cu + 4];
            Qh1[c][3] = qp[(g + 24) * 32 + cu + 4];
        }
    }

    float4 Oc0[8], Oc1[8];
#pragma unroll
    for (int j = 0; j < 8; j++) {
        Oc0[j] = make_float4(0.f, 0.f, 0.f, 0.f);
        Oc1[j] = make_float4(0.f, 0.f, 0.f, 0.f);
    }
    float mr[4] = {-1e30f, -1e30f, -1e30f, -1e30f};
    float lr[4] = {0.f, 0.f, 0.f, 0.f};

    const uint32_t* ksrc = g_ksw + (size_t)bh * 32 * 2048;
    const uint32_t* vsrc = g_vsw + (size_t)bh * 32 * 2048;
    const float* bp = bias + ((size_t)b * 2048 + qt * 128 + wid * 32) * 2048;
    const unsigned char* mp = g_mask + b * 2048;

    {
#pragma unroll
        for (int i = 0; i < 4; i++) {
            cpasync16(smu + (tid + i * 128) * 4, ksrc + (size_t)(tid + i * 128) * 4);
            cpasync16(smu + 2048 + (tid + i * 128) * 4, vsrc + (size_t)(tid + i * 128) * 4);
        }
        cp_commit();
    }

    for (int kt = 0; kt < 32; kt++) {
        __syncthreads();
        if (kt + 1 < 32) {
            uint32_t* dstb = smu + ((kt + 1) & 1) * 4096;
            const uint32_t* kg = ksrc + (size_t)(kt + 1) * 2048;
            const uint32_t* vg = vsrc + (size_t)(kt + 1) * 2048;
#pragma unroll
            for (int i = 0; i < 4; i++) {
                cpasync16(dstb + (tid + i * 128) * 4, kg + (size_t)(tid + i * 128) * 4);
                cpasync16(dstb + 2048 + (tid + i * 128) * 4, vg + (size_t)(tid + i * 128) * 4);
            }
            cp_commit();
            cp_wait<1>();
        } else {
            cp_wait<0>();
        }
        __syncthreads();

        const uint4* Kf4 = (const uint4*)(smu + (kt & 1) * 4096);
        const uint4* Vf4 = Kf4 + 512;
        const float* bt = bp + kt * 64;

        float4 Sc0[8], Sc1[8];
#pragma unroll
        for (int j = 0; j < 8; j++) {
            uchar2 mk = *(const uchar2*)(mp + kt * 64 + j * 8 + 2 * tg);
            float2 b0 = *(const float2*)(bt + (size_t)g * 2048 + j * 8 + 2 * tg);
            float2 b1 = *(const float2*)(bt + (size_t)(g + 8) * 2048 + j * 8 + 2 * tg);
            float2 b2 = *(const float2*)(bt + (size_t)(g + 16) * 2048 + j * 8 + 2 * tg);
            float2 b3 = *(const float2*)(bt + (size_t)(g + 24) * 2048 + j * 8 + 2 * tg);
            uint4 kA = Kf4[(j * 2 + 0) * 32 + lane];
            uint4 kB = Kf4[(j * 2 + 1) * 32 + lane];
            float4 c0 = make_float4(0.f, 0.f, 0.f, 0.f);
            float4 c1 = make_float4(0.f, 0.f, 0.f, 0.f);
            mma16(c0, Qh0[0], kA.x, kA.y);
            mma16(c0, Qh0[1], kA.z, kA.w);
            mma16(c0, Qh0[2], kB.x, kB.y);
            mma16(c0, Qh0[3], kB.z, kB.w);
            mma16(c1, Qh1[0], kA.x, kA.y);
            mma16(c1, Qh1[1], kA.z, kA.w);
            mma16(c1, Qh1[2], kB.x, kB.y);
            mma16(c1, Qh1[3], kB.z, kB.w);
            c0.x = mk.x ? -1e9f : fmaf(gamma, b0.x, c0.x);
            c0.y = mk.y ? -1e9f : fmaf(gamma, b0.y, c0.y);
            c0.z = mk.x ? -1e9f : fmaf(gamma, b1.x, c0.z);
            c0.w = mk.y ? -1e9f : fmaf(gamma, b1.y, c0.w);
            c1.x = mk.x ? -1e9f : fmaf(gamma, b2.x, c1.x);
            c1.y = mk.y ? -1e9f : fmaf(gamma, b2.y, c1.y);
            c1.z = mk.x ? -1e9f : fmaf(gamma, b3.x, c1.z);
            c1.w = mk.y ? -1e9f : fmaf(gamma, b3.y, c1.w);
            Sc0[j] = c0;
            Sc1[j] = c1;
        }

        float tm[4] = {-1e30f, -1e30f, -1e30f, -1e30f};
#pragma unroll
        for (int j = 0; j < 8; j++) {
            tm[0] = fmaxf(tm[0], fmaxf(Sc0[j].x, Sc0[j].y));
            tm[1] = fmaxf(tm[1], fmaxf(Sc0[j].z, Sc0[j].w));
            tm[2] = fmaxf(tm[2], fmaxf(Sc1[j].x, Sc1[j].y));
            tm[3] = fmaxf(tm[3], fmaxf(Sc1[j].z, Sc1[j].w));
        }
        float sc[4];
#pragma unroll
        for (int r = 0; r < 4; r++) {
            tm[r] = fmaxf(tm[r], __shfl_xor_sync(0xffffffffu, tm[r], 1));
            tm[r] = fmaxf(tm[r], __shfl_xor_sync(0xffffffffu, tm[r], 2));
            float mn = fmaxf(mr[r], tm[r]);
            sc[r] = __expf(mr[r] - mn);
            mr[r] = mn;
        }
        float rs[4] = {0.f, 0.f, 0.f, 0.f};
#pragma unroll
        for (int j = 0; j < 8; j++) {
            Sc0[j].x = __expf(Sc0[j].x - mr[0]);
            Sc0[j].y = __expf(Sc0[j].y - mr[0]);
            Sc0[j].z = __expf(Sc0[j].z - mr[1]);
            Sc0[j].w = __expf(Sc0[j].w - mr[1]);
            Sc1[j].x = __expf(Sc1[j].x - mr[2]);
            Sc1[j].y = __expf(Sc1[j].y - mr[2]);
            Sc1[j].z = __expf(Sc1[j].z - mr[3]);
            Sc1[j].w = __expf(Sc1[j].w - mr[3]);
            rs[0] += Sc0[j].x + Sc0[j].y;
            rs[1] += Sc0[j].z + Sc0[j].w;
            rs[2] += Sc1[j].x + Sc1[j].y;
            rs[3] += Sc1[j].z + Sc1[j].w;
        }
#pragma unroll
        for (int r = 0; r < 4; r++) {
            rs[r] += __shfl_xor_sync(0xffffffffu, rs[r], 1);
            rs[r] += __shfl_xor_sync(0xffffffffu, rs[r], 2);
            lr[r] = lr[r] * sc[r] + rs[r];
        }
#pragma unroll
        for (int j = 0; j < 8; j++) {
            Oc0[j].x *= sc[0]; Oc0[j].y *= sc[0];
            Oc0[j].z *= sc[1]; Oc0[j].w *= sc[1];
            Oc1[j].x *= sc[2]; Oc1[j].y *= sc[2];
            Oc1[j].z *= sc[3]; Oc1[j].w *= sc[3];
        }

        uint32_t Pa0[4][4], Pa1[4][4];
#pragma unroll
        for (int c = 0; c < 4; c++) {
            Pa0[c][0] = pkbf(Sc0[2*c].x,     Sc0[2*c].y);
            Pa0[c][1] = pkbf(Sc0[2*c].z,     Sc0[2*c].w);
            Pa0[c][2] = pkbf(Sc0[2*c + 1].x, Sc0[2*c + 1].y);
            Pa0[c][3] = pkbf(Sc0[2*c + 1].z, Sc0[2*c + 1].w);
            Pa1[c][0] = pkbf(Sc1[2*c].x,     Sc1[2*c].y);
            Pa1[c][1] = pkbf(Sc1[2*c].z,     Sc1[2*c].w);
            Pa1[c][2] = pkbf(Sc1[2*c + 1].x, Sc1[2*c + 1].y);
            Pa1[c][3] = pkbf(Sc1[2*c + 1].z, Sc1[2*c + 1].w);
        }

#pragma unroll
        for (int j = 0; j < 8; j++) {
            uint4 vA = Vf4[(j * 2 + 0) * 32 + lane];
            uint4 vB = Vf4[(j * 2 + 1) * 32 + lane];
            mma16(Oc0[j], Pa0[0], vA.x, vA.y);
            mma16(Oc0[j], Pa0[1], vA.z, vA.w);
            mma16(Oc0[j], Pa0[2], vB.x, vB.y);
            mma16(Oc0[j], Pa0[3], vB.z, vB.w);
            mma16(Oc1[j], Pa1[0], vA.x, vA.y);
            mma16(Oc1[j], Pa1[1], vA.z, vA.w);
            mma16(Oc1[j], Pa1[2], vB.x, vB.y);
            mma16(Oc1[j], Pa1[3], vB.z, vB.w);
        }
    }

    const float i0 = 1.f / lr[0], i1 = 1.f / lr[1];
    const float i2 = 1.f / lr[2], i3 = 1.f / lr[3];
    float* op = g_att + ((size_t)b * 2048 + qt * 128 + wid * 32) * 512 + h * 64;
#pragma unroll
    for (int j = 0; j < 8; j++) {
        int col = j * 8 + 2 * tg;
        *(float2*)(op + (size_t)g * 512 + col) =
            make_float2(Oc0[j].x * i0, Oc0[j].y * i0);
        *(float2*)(op + (size_t)(g + 8) * 512 + col) =
            make_float2(Oc0[j].z * i1, Oc0[j].w * i1);
        *(float2*)(op + (size_t)(g + 16) * 512 + col) =
            make_float2(Oc1[j].x * i2, Oc1[j].y * i2);
        *(float2*)(op + (size_t)(g + 24) * 512 + col) =
            make_float2(Oc1[j].z * i3, Oc1[j].w * i3);
    }
}

// ---------------------------------------------------------------------------
// LayerNorm in-place on d_out
// ---------------------------------------------------------------------------
__global__ __launch_bounds__(128) void ln_kernel(
    float* __restrict__ y, const float* __restrict__ g,
    const float* __restrict__ be)
{
    const int row = blockIdx.x;
    const int tid = threadIdx.x;
    float4 v = *(const float4*)(y + (size_t)row * 512 + tid * 4);
    float s = (v.x + v.y) + (v.z + v.w);
    float q = (v.x * v.x + v.y * v.y) + (v.z * v.z + v.w * v.w);
#pragma unroll
    for (int msk = 16; msk; msk >>= 1) {
        s += __shfl_xor_sync(0xffffffffu, s, msk);
        q += __shfl_xor_sync(0xffffffffu, q, msk);
    }
    __shared__ float ss[4], sq[4];
    const int w = tid >> 5;
    if ((tid & 31) == 0) { ss[w] = s; sq[w] = q; }
    __syncthreads();
    s = (ss[0] + ss[1]) + (ss[2] + ss[3]);
    q = (sq[0] + sq[1]) + (sq[2] + sq[3]);
    const float mu = s * (1.0f / 512.0f);
    const float var = q * (1.0f / 512.0f) - mu * mu;
    const float rs = rsqrtf(var + 1e-5f);
    float4 gg = *(const float4*)(g + tid * 4);
    float4 bb = *(const float4*)(be + tid * 4);
    float4 r;
    r.x = (v.x - mu) * rs * gg.x + bb.x;
    r.y = (v.y - mu) * rs * gg.y + bb.y;
    r.z = (v.z - mu) * rs * gg.z + bb.z;
    r.w = (v.w - mu) * rs * gg.w + bb.w;
    *(float4*)(y + (size_t)row * 512 + tid * 4) = r;
}

// ---------------------------------------------------------------------------
extern "C" void kernel_launch(void* const* d_in, const int* in_sizes, int n_in,
                              void* d_out, int out_size)
{
    const float* xp      = (const float*)d_in[0];
    const float* xpcre   = (const float*)d_in[1];
    const float* bias    = (const float*)d_in[2];
    const void*  mask    = d_in[3];
    const float* Wq      = (const float*)d_in[4];
    const float* Wkv     = (const float*)d_in[5];
    const float* Wff     = (const float*)d_in[6];
    const float* bff     = (const float*)d_in[7];
    const float* gamma_f = (const float*)d_in[8];
    const float* ln_g    = (const float*)d_in[9];
    const float* ln_b    = (const float*)d_in[10];
    float* out = (float*)d_out;

    const int attn_smem = 2 * 4096 * 4;     // 32768 B
    const int proj_smem = 2 * PSTG * 4;     // 40960 B
    const int gemm_smem = 2 * STG_F * 4;    // 37888 B
    cudaFuncSetAttribute(attn_mma_kernel,
                         cudaFuncAttributeMaxDynamicSharedMemorySize, attn_smem);
    cudaFuncSetAttribute(proj_bf_kernel,
                         cudaFuncAttributeMaxDynamicSharedMemorySize, proj_smem);
    cudaFuncSetAttribute(ff_tc_kernel,
                         cudaFuncAttributeMaxDynamicSharedMemorySize, gemm_smem);

    mask_norm_kernel<<<1, 256>>>(mask);
    conv_x_kernel<<<BB * SS, 256>>>(xp, xpcre);     // 16384 blocks x 256 = N/256
    dim3 wg(32, 16, 2);
    conv_w_kernel<<<wg, 256>>>(Wq, Wkv);

    dim3 pg(12, 128);
    proj_bf_kernel<<<pg, 256, proj_smem>>>();

    dim3 rg(32, 64, 2);
    repack_kv_kernel<<<rg, 256>>>();

    dim3 ag(16, 8, 8);   // (qtile128, h, b), 4 warps x 32 rows
    attn_mma_kernel<<<ag, 128, attn_smem>>>(bias, gamma_f);

    dim3 fg(4, 128);
    ff_tc_kernel<<<fg, 256, gemm_smem>>>(Wff, bff, xp, out);

    ln_kernel<<<BB * SS, 128>>>(out, ln_g, ln_b);
}

// round 16
// speedup vs baseline: 5.4248x; 1.0467x over previous
#include <cuda_runtime.h>
#include <cuda_bf16.h>
#include <cstdint>

#define BB 8
#define SS 2048
#define DE 512
#define HH 8
#define DH 64

// Scratch (allocation-free: device globals)
__device__ __align__(16) uint32_t g_xh[BB*SS*256];    // x_p   bf16x2 [m][256]
__device__ __align__(16) uint32_t g_xch[BB*SS*256];   // x_pcre bf16x2
__device__ __align__(16) uint32_t g_wqt[512*256];     // Wq^T  bf16x2 [n][k/2]
__device__ __align__(16) uint32_t g_wkvt[1024*256];   // Wkv^T bf16x2 [n][k/2]
__device__ __align__(16) uint32_t g_qh[BB*HH*SS*32];  // q bf16x2 [bh][s][d/2] (pre-scaled 1/8)
__device__ __align__(16) uint32_t g_kh[BB*HH*SS*32];  // k bf16x2
__device__ __align__(16) uint32_t g_vh[BB*HH*SS*32];  // v bf16x2
__device__ float g_att[BB*SS*DE];                     // [b][s][h*64+d] fp32
__device__ unsigned char g_mask[BB*SS];
// bf16 m16n8k16 B-fragment layout per 64x64 tile:
//   [fg(16)=(blk8,kc2)][lane(32)][4 u32]
__device__ __align__(16) uint32_t g_ksw[BB*HH*32*2048];
__device__ __align__(16) uint32_t g_vsw[BB*HH*32*2048];

// ---------------------------------------------------------------------------
// small helpers
// ---------------------------------------------------------------------------
__device__ __forceinline__ uint32_t f2tf32(float f) {
    uint32_t u;
    asm("cvt.rna.tf32.f32 %0, %1;" : "=r"(u) : "f"(f));
    return u;
}
// pack two floats to bf16x2: lo = a (element 0), hi = b (element 1)
__device__ __forceinline__ uint32_t pkbf(float lo, float hi) {
    uint32_t r;
    asm("cvt.rn.bf16x2.f32 %0, %1, %2;" : "=r"(r) : "f"(hi), "f"(lo));
    return r;
}
__device__ __forceinline__ void mma8(float4& c, const uint32_t a[4],
                                     uint32_t b0, uint32_t b1) {
    asm volatile(
        "mma.sync.aligned.m16n8k8.row.col.f32.tf32.tf32.f32 "
        "{%0,%1,%2,%3},{%4,%5,%6,%7},{%8,%9},{%0,%1,%2,%3};"
        : "+f"(c.x), "+f"(c.y), "+f"(c.z), "+f"(c.w)
        : "r"(a[0]), "r"(a[1]), "r"(a[2]), "r"(a[3]), "r"(b0), "r"(b1));
}
__device__ __forceinline__ void mma16(float4& c, const uint32_t a[4],
                                      uint32_t b0, uint32_t b1) {
    asm volatile(
        "mma.sync.aligned.m16n8k16.row.col.f32.bf16.bf16.f32 "
        "{%0,%1,%2,%3},{%4,%5,%6,%7},{%8,%9},{%0,%1,%2,%3};"
        : "+f"(c.x), "+f"(c.y), "+f"(c.z), "+f"(c.w)
        : "r"(a[0]), "r"(a[1]), "r"(a[2]), "r"(a[3]), "r"(b0), "r"(b1));
}
__device__ __forceinline__ void cpasync16(void* s, const void* g) {
    uint32_t sa = (uint32_t)__cvta_generic_to_shared(s);
    asm volatile("cp.async.cg.shared.global [%0], [%1], 16;" :: "r"(sa), "l"(g));
}
__device__ __forceinline__ void cp_commit() {
    asm volatile("cp.async.commit_group;" ::: "memory");
}
template <int N>
__device__ __forceinline__ void cp_wait() {
    asm volatile("cp.async.wait_group %0;" :: "n"(N) : "memory");
}

// ---------------------------------------------------------------------------
// Mask dtype probe + normalize
// ---------------------------------------------------------------------------
__global__ void mask_norm_kernel(const void* __restrict__ mraw)
{
    __shared__ int s_nz, s_3f;
    const int tid = threadIdx.x;
    if (tid == 0) { s_nz = 0; s_3f = 0; }
    __syncthreads();
    const unsigned char* u8 = (const unsigned char*)mraw;
    int nz = 0, c3 = 0;
    for (int i = tid; i < BB*SS; i += 256) {
        unsigned char c = u8[i];
        nz += (c != 0);
        c3 += (c == 0x3F);
    }
    atomicAdd(&s_nz, nz);
    atomicAdd(&s_3f, c3);
    __syncthreads();
    int mode = (s_3f > 100) ? 2 : ((s_nz > 1000) ? 0 : 1);
    for (int i = tid; i < BB*SS; i += 256) {
        unsigned char m;
        if (mode == 2)      m = (((const float*)mraw)[i] != 0.0f);
        else if (mode == 1) m = (((const int*)mraw)[i] != 0);
        else                m = (u8[i] != 0);
        g_mask[i] = m;
    }
}

// ---------------------------------------------------------------------------
// Prep: convert x_p / x_pcre to bf16x2
// ---------------------------------------------------------------------------
__global__ __launch_bounds__(256) void conv_x_kernel(
    const float* __restrict__ xp, const float* __restrict__ xc)
{
    const int idx = blockIdx.x * 256 + threadIdx.x;   // < BB*SS*256
    float2 a = ((const float2*)xp)[idx];
    float2 b = ((const float2*)xc)[idx];
    g_xh[idx]  = pkbf(a.x, a.y);
    g_xch[idx] = pkbf(b.x, b.y);
}

// ---------------------------------------------------------------------------
// Prep: transpose W (fp32 [k][n]) -> bf16x2 [n][k/2]
// z=0: Wq (512x512), z=1: Wkv (512x1024)
// ---------------------------------------------------------------------------
__global__ __launch_bounds__(256) void conv_w_kernel(
    const float* __restrict__ Wq, const float* __restrict__ Wkv)
{
    const int z = blockIdx.z;
    const float* W = z ? Wkv : Wq;
    const int ldn = z ? 1024 : 512;
    uint32_t* out = z ? g_wkvt : g_wqt;
    const int n0 = blockIdx.x * 32, k0 = blockIdx.y * 32;
    if (n0 >= ldn) return;
    __shared__ float ts[32][33];
    const int tx = threadIdx.x & 31, ty = threadIdx.x >> 5;
#pragma unroll
    for (int r = 0; r < 4; r++)
        ts[ty + r * 8][tx] = W[(size_t)(k0 + ty + r * 8) * ldn + n0 + tx];
    __syncthreads();
#pragma unroll
    for (int i = 0; i < 2; i++) {
        int e = threadIdx.x + i * 256;
        int n = e >> 4, j = e & 15;
        out[(size_t)(n0 + n) * 256 + (k0 >> 1) + j] = pkbf(ts[2*j][n], ts[2*j+1][n]);
    }
}

// ---------------------------------------------------------------------------
// QKV projection, bf16 m16n8k16. CTA 128x128, k32/stage, double-buffered.
// ---------------------------------------------------------------------------
#define PSTG 5120   // u32 per stage: A 128*20 + B 128*20

__global__ __launch_bounds__(256) void proj_bf_kernel()
{
    extern __shared__ __align__(16) uint32_t su[];
    const int nt = blockIdx.x, mt = blockIdx.y;
    const int grp = nt >> 2;
    const int ncol0 = (nt & 3) * 128;
    const uint32_t* __restrict__ A  = (grp == 0) ? g_xh : g_xch;
    const uint32_t* __restrict__ Wt = (grp == 0) ? g_wqt : g_wkvt;
    const int wr0 = (grp == 2) ? (512 + ncol0) : ncol0;
    uint32_t* dst = (grp == 0) ? g_qh : ((grp == 1) ? g_kh : g_vh);
    const float osc = (grp == 0) ? 0.125f : 1.0f;

    const int tid = threadIdx.x, wid = tid >> 5, lane = tid & 31;
    const int g = lane >> 2, tg = lane & 3;
    const int wm = wid >> 2, wn = wid & 3;
    const int m0 = mt * 128;

    float4 C[4][4];
#pragma unroll
    for (int mi = 0; mi < 4; mi++)
#pragma unroll
        for (int ni = 0; ni < 4; ni++) C[mi][ni] = make_float4(0.f,0.f,0.f,0.f);

    auto stage_load = [&](uint32_t* S, int k0u) {
        uint32_t* Sb = S + 2560;
#pragma unroll
        for (int i = 0; i < 2; i++) {
            int e = tid + i * 256;
            int row = e >> 2, cq = (e & 3) * 4;
            cpasync16(S + row * 20 + cq, A + (size_t)(m0 + row) * 256 + k0u + cq);
            cpasync16(Sb + row * 20 + cq, Wt + (size_t)(wr0 + row) * 256 + k0u + cq);
        }
    };

    stage_load(su, 0);
    cp_commit();

    for (int kt = 0; kt < 16; kt++) {
        __syncthreads();
        if (kt + 1 < 16) {
            stage_load(su + ((kt + 1) & 1) * PSTG, (kt + 1) * 16);
            cp_commit();
            cp_wait<1>();
        } else {
            cp_wait<0>();
        }
        __syncthreads();
        const uint32_t* Sa = su + (kt & 1) * PSTG;
        const uint32_t* Sb = Sa + 2560;
#pragma unroll
        for (int ks = 0; ks < 2; ks++) {
            const int base = ks * 8;
            uint32_t a[4][4];
#pragma unroll
            for (int mi = 0; mi < 4; mi++) {
                const uint32_t* ap = Sa + (wm * 64 + mi * 16) * 20 + base + tg;
                a[mi][0] = ap[g * 20];
                a[mi][1] = ap[(g + 8) * 20];
                a[mi][2] = ap[g * 20 + 4];
                a[mi][3] = ap[(g + 8) * 20 + 4];
            }
            uint32_t bf[4][2];
#pragma unroll
            for (int ni = 0; ni < 4; ni++) {
                const uint32_t* bp = Sb + (wn * 32 + ni * 8 + g) * 20 + base + tg;
                bf[ni][0] = bp[0];
                bf[ni][1] = bp[4];
            }
#pragma unroll
            for (int mi = 0; mi < 4; mi++)
#pragma unroll
                for (int ni = 0; ni < 4; ni++)
                    mma16(C[mi][ni], a[mi], bf[ni][0], bf[ni][1]);
        }
    }

#pragma unroll
    for (int mi = 0; mi < 4; mi++) {
        int r0 = m0 + wm * 64 + mi * 16 + g;
        int r1 = r0 + 8;
        int b0 = r0 >> 11, s0 = r0 & 2047;
        int b1 = r1 >> 11, s1 = r1 & 2047;
#pragma unroll
        for (int ni = 0; ni < 4; ni++) {
            int col = ncol0 + wn * 32 + ni * 8 + 2 * tg;
            int h = col >> 6, d = col & 63;
            float4 c = C[mi][ni];
            dst[((size_t)(b0 * 8 + h) * 2048 + s0) * 32 + (d >> 1)] =
                pkbf(c.x * osc, c.y * osc);
            dst[((size_t)(b1 * 8 + h) * 2048 + s1) * 32 + (d >> 1)] =
                pkbf(c.z * osc, c.w * osc);
        }
    }
}

// ===========================================================================
// tf32 GEMM core (ff only): CTA 128x128, K-step 16, double-buffered.
// ===========================================================================
#define STG_F (128*20 + 16*136)   // 4736 floats per stage

struct Frag16 {
    float4 c[4][4];
};

__device__ __forceinline__ void gemm_stage_load(
    float* Sa, const float* __restrict__ A, const float* __restrict__ W,
    int m0, int k0, int ldw, int wc0, int tid)
{
    float* Sb = Sa + 128*20;
#pragma unroll
    for (int i = 0; i < 2; i++) {
        int e = tid + i * 256;
        int row = e >> 2, kq = (e & 3) * 4;
        cpasync16(Sa + row * 20 + kq, A + (size_t)(m0 + row) * 512 + k0 + kq);
    }
#pragma unroll
    for (int i = 0; i < 2; i++) {
        int e = tid + i * 256;
        int row = e >> 5, nq = (e & 31) * 4;
        cpasync16(Sb + row * 136 + nq, W + (size_t)(k0 + row) * ldw + wc0 + nq);
    }
}

__device__ __forceinline__ void gemm_compute_stage(
    Frag16& F, const float* Sa, int wm, int wn, int g, int tg)
{
    const float* Sb = Sa + 128*20;
#pragma unroll
    for (int ks = 0; ks < 2; ks++) {
        uint32_t a[4][4];
#pragma unroll
        for (int mi = 0; mi < 4; mi++) {
            const float* ap = Sa + (wm * 64 + mi * 16) * 20 + ks * 8 + tg;
            a[mi][0] = f2tf32(ap[g * 20]);
            a[mi][1] = f2tf32(ap[(g + 8) * 20]);
            a[mi][2] = f2tf32(ap[g * 20 + 4]);
            a[mi][3] = f2tf32(ap[(g + 8) * 20 + 4]);
        }
        uint32_t bf[4][2];
#pragma unroll
        for (int ni = 0; ni < 4; ni++) {
            const float* bp = Sb + (ks * 8 + tg) * 136 + wn * 32 + ni * 8 + g;
            bf[ni][0] = f2tf32(bp[0]);
            bf[ni][1] = f2tf32(bp[4 * 136]);
        }
#pragma unroll
        for (int mi = 0; mi < 4; mi++)
#pragma unroll
            for (int ni = 0; ni < 4; ni++)
                mma8(F.c[mi][ni], a[mi], bf[ni][0], bf[ni][1]);
    }
}

// ---------------------------------------------------------------------------
// FF, tf32 mma: y = x_p + att @ Wff + bff. grid (4 nt, 128 mt).
// ---------------------------------------------------------------------------
__global__ __launch_bounds__(256) void ff_tc_kernel(
    const float* __restrict__ Wff, const float* __restrict__ bff,
    const float* __restrict__ xp, float* __restrict__ out)
{
    extern __shared__ __align__(16) float sm[];
    const int nt = blockIdx.x, mt = blockIdx.y;
    const int ncol0 = nt * 128;
    const int tid = threadIdx.x, wid = tid >> 5, lane = tid & 31;
    const int g = lane >> 2, tg = lane & 3;
    const int wm = wid >> 2, wn = wid & 3;
    const int m0 = mt * 128;

    Frag16 F;
#pragma unroll
    for (int mi = 0; mi < 4; mi++)
#pragma unroll
        for (int ni = 0; ni < 4; ni++) F.c[mi][ni] = make_float4(0.f,0.f,0.f,0.f);

    gemm_stage_load(sm, g_att, Wff, m0, 0, 512, ncol0, tid);
    cp_commit();

    for (int kt = 0; kt < 32; kt++) {
        __syncthreads();
        if (kt + 1 < 32) {
            gemm_stage_load(sm + ((kt + 1) & 1) * STG_F, g_att, Wff, m0,
                            (kt + 1) * 16, 512, ncol0, tid);
            cp_commit();
            cp_wait<1>();
        } else {
            cp_wait<0>();
        }
        __syncthreads();
        gemm_compute_stage(F, sm + (kt & 1) * STG_F, wm, wn, g, tg);
    }

#pragma unroll
    for (int mi = 0; mi < 4; mi++) {
        int r0 = m0 + wm * 64 + mi * 16 + g;
        int r1 = r0 + 8;
#pragma unroll
        for (int ni = 0; ni < 4; ni++) {
            int col = ncol0 + wn * 32 + ni * 8 + 2 * tg;
            float4 c = F.c[mi][ni];
            float2 bb = *(const float2*)(bff + col);
            float2 x0 = *(const float2*)(xp + (size_t)r0 * 512 + col);
            float2 x1 = *(const float2*)(xp + (size_t)r1 * 512 + col);
            float2 o0 = make_float2(c.x + bb.x + x0.x, c.y + bb.y + x0.y);
            float2 o1 = make_float2(c.z + bb.x + x1.x, c.w + bb.y + x1.y);
            *(float2*)(out + (size_t)r0 * 512 + col) = o0;
            *(float2*)(out + (size_t)r1 * 512 + col) = o1;
        }
    }
}

// ---------------------------------------------------------------------------
// Repack K and V (bf16x2 in) into m16n8k16 B-fragment layout. No cvt.
// ---------------------------------------------------------------------------
__global__ __launch_bounds__(256) void repack_kv_kernel()
{
    const int kt = blockIdx.x, bh = blockIdx.y, kind = blockIdx.z;
    __shared__ uint32_t ts[64][33];
    const uint32_t* src = (kind ? g_vh : g_kh) + ((size_t)bh * 2048 + kt * 64) * 32;
    const int tid = threadIdx.x;
#pragma unroll
    for (int i = 0; i < 2; i++) {
        int e = tid + i * 256;
        int row = e >> 3, c4 = (e & 7) * 4;
        uint4 v = *(const uint4*)(src + row * 32 + c4);
        ts[row][c4 + 0] = v.x; ts[row][c4 + 1] = v.y;
        ts[row][c4 + 2] = v.z; ts[row][c4 + 3] = v.w;
    }
    __syncthreads();
    const int w = tid >> 5, lane = tid & 31, g = lane >> 2, tg = lane & 3;
    uint4* dst4 = (uint4*)((kind ? g_vsw : g_ksw) + ((size_t)bh * 32 + kt) * 2048);
#pragma unroll
    for (int i = 0; i < 2; i++) {
        int fg = w + i * 8;           // 0..15
        int blk = fg >> 1, kc2 = fg & 1;
        uint4 o;
        uint32_t* op = (uint32_t*)&o;
#pragma unroll
        for (int r = 0; r < 4; r++) {
            if (kind == 0) {
                int cu = (kc2 * 2 + (r >> 1)) * 8 + (r & 1) * 4 + tg;
                op[r] = ts[blk * 8 + g][cu];
            } else {
                int e0 = (kc2 * 2 + (r >> 1)) * 16 + (r & 1) * 8 + 2 * tg;
                int d  = blk * 8 + g;
                uint32_t x0 = ts[e0][d >> 1];
                uint32_t x1 = ts[e0 + 1][d >> 1];
                op[r] = __byte_perm(x0, x1, (d & 1) ? 0x7632 : 0x5410);
            }
        }
        dst4[fg * 32 + lane] = o;
    }
}

// ---------------------------------------------------------------------------
// Flash attention, bf16 m16n8k16 mma. CTA = 4 warps x 32 q-rows = 128 rows.
// K/V AND bias staged via cp.async double-buffer; hot loop is pure LDS+mma.
// stage (u32): K 2048 | V 2048 | bias 128 rows x 72 f32 (pad 72 -> 2-phase LDS)
// ---------------------------------------------------------------------------
#define ASTG 13312   // u32 per stage: 4096 KV + 9216 bias

__global__ __launch_bounds__(128, 2) void attn_mma_kernel(
    const float* __restrict__ bias, const float* __restrict__ gamma_f)
{
    extern __shared__ __align__(16) uint32_t smu[];   // 2 stages x ASTG u32
    const int qt = blockIdx.x, h = blockIdx.y, b = blockIdx.z;
    const int bh = b * 8 + h;
    const int tid = threadIdx.x, wid = tid >> 5, lane = tid & 31;
    const int g = lane >> 2, tg = lane & 3;
    const float gamma = __ldg(gamma_f + h);

    // Q fragments: direct u32 loads (bf16x2, d-pairs contiguous)
    uint32_t Qh0[4][4], Qh1[4][4];
    {
        const uint32_t* qp = g_qh + ((size_t)bh * 2048 + qt * 128 + wid * 32) * 32;
#pragma unroll
        for (int c = 0; c < 4; c++) {
            int cu = c * 8 + tg;
            Qh0[c][0] = qp[g * 32 + cu];
            Qh0[c][1] = qp[(g + 8) * 32 + cu];
            Qh0[c][2] = qp[g * 32 + cu + 4];
            Qh0[c][3] = qp[(g + 8) * 32 + cu + 4];
            Qh1[c][0] = qp[(g + 16) * 32 + cu];
            Qh1[c][1] = qp[(g + 24) * 32 + cu];
            Qh1[c][2] = qp[(g + 16) * 32 + cu + 4];
            Qh1[c][3] = qp[(g + 24) * 32 + cu + 4];
        }
    }

    float4 Oc0[8], Oc1[8];
#pragma unroll
    for (int j = 0; j < 8; j++) {
        Oc0[j] = make_float4(0.f, 0.f, 0.f, 0.f);
        Oc1[j] = make_float4(0.f, 0.f, 0.f, 0.f);
    }
    float mr[4] = {-1e30f, -1e30f, -1e30f, -1e30f};
    float lr[4] = {0.f, 0.f, 0.f, 0.f};

    const uint32_t* ksrc = g_ksw + (size_t)bh * 32 * 2048;
    const uint32_t* vsrc = g_vsw + (size_t)bh * 32 * 2048;
    const float* bsrc = bias + ((size_t)b * 2048 + qt * 128) * 2048;  // [row][2048]
    const unsigned char* mp = g_mask + b * 2048;

    // stage filler: KV (8 cpasync) + bias 128x64 f32 (16 cpasync)
    auto stage_fill = [&](int st, int kt) {
        uint32_t* dstb = smu + st * ASTG;
        const uint32_t* kg = ksrc + (size_t)kt * 2048;
        const uint32_t* vg = vsrc + (size_t)kt * 2048;
#pragma unroll
        for (int i = 0; i < 4; i++) {
            cpasync16(dstb + (tid + i * 128) * 4, kg + (size_t)(tid + i * 128) * 4);
            cpasync16(dstb + 2048 + (tid + i * 128) * 4, vg + (size_t)(tid + i * 128) * 4);
        }
        float* bdst = (float*)(dstb + 4096);
        const float* bg = bsrc + kt * 64;
#pragma unroll
        for (int i = 0; i < 16; i++) {
            int e = tid + i * 128;
            int row = e >> 4, seg = e & 15;
            cpasync16(bdst + row * 72 + seg * 4, bg + (size_t)row * 2048 + seg * 4);
        }
    };

    stage_fill(0, 0);
    cp_commit();

    for (int kt = 0; kt < 32; kt++) {
        __syncthreads();
        if (kt + 1 < 32) {
            stage_fill((kt + 1) & 1, kt + 1);
            cp_commit();
            cp_wait<1>();
        } else {
            cp_wait<0>();
        }
        __syncthreads();

        const uint4* Kf4 = (const uint4*)(smu + (kt & 1) * ASTG);
        const uint4* Vf4 = Kf4 + 512;
        const float* bsm = (const float*)(smu + (kt & 1) * ASTG + 4096)
                           + (wid * 32 + g) * 72 + 2 * tg;

        float4 Sc0[8], Sc1[8];
#pragma unroll
        for (int j = 0; j < 8; j++) {
            uchar2 mk = *(const uchar2*)(mp + kt * 64 + j * 8 + 2 * tg);
            float2 b0 = *(const float2*)(bsm + j * 8);
            float2 b1 = *(const float2*)(bsm + 576 + j * 8);    //  +8 rows
            float2 b2 = *(const float2*)(bsm + 1152 + j * 8);   // +16 rows
            float2 b3 = *(const float2*)(bsm + 1728 + j * 8);   // +24 rows
            uint4 kA = Kf4[(j * 2 + 0) * 32 + lane];
            uint4 kB = Kf4[(j * 2 + 1) * 32 + lane];
            float4 c0 = make_float4(0.f, 0.f, 0.f, 0.f);
            float4 c1 = make_float4(0.f, 0.f, 0.f, 0.f);
            mma16(c0, Qh0[0], kA.x, kA.y);
            mma16(c0, Qh0[1], kA.z, kA.w);
            mma16(c0, Qh0[2], kB.x, kB.y);
            mma16(c0, Qh0[3], kB.z, kB.w);
            mma16(c1, Qh1[0], kA.x, kA.y);
            mma16(c1, Qh1[1], kA.z, kA.w);
            mma16(c1, Qh1[2], kB.x, kB.y);
            mma16(c1, Qh1[3], kB.z, kB.w);
            c0.x = mk.x ? -1e9f : fmaf(gamma, b0.x, c0.x);
            c0.y = mk.y ? -1e9f : fmaf(gamma, b0.y, c0.y);
            c0.z = mk.x ? -1e9f : fmaf(gamma, b1.x, c0.z);
            c0.w = mk.y ? -1e9f : fmaf(gamma, b1.y, c0.w);
            c1.x = mk.x ? -1e9f : fmaf(gamma, b2.x, c1.x);
            c1.y = mk.y ? -1e9f : fmaf(gamma, b2.y, c1.y);
            c1.z = mk.x ? -1e9f : fmaf(gamma, b3.x, c1.z);
            c1.w = mk.y ? -1e9f : fmaf(gamma, b3.y, c1.w);
            Sc0[j] = c0;
            Sc1[j] = c1;
        }

        float tm[4] = {-1e30f, -1e30f, -1e30f, -1e30f};
#pragma unroll
        for (int j = 0; j < 8; j++) {
            tm[0] = fmaxf(tm[0], fmaxf(Sc0[j].x, Sc0[j].y));
            tm[1] = fmaxf(tm[1], fmaxf(Sc0[j].z, Sc0[j].w));
            tm[2] = fmaxf(tm[2], fmaxf(Sc1[j].x, Sc1[j].y));
            tm[3] = fmaxf(tm[3], fmaxf(Sc1[j].z, Sc1[j].w));
        }
        float sc[4];
#pragma unroll
        for (int r = 0; r < 4; r++) {
            tm[r] = fmaxf(tm[r], __shfl_xor_sync(0xffffffffu, tm[r], 1));
            tm[r] = fmaxf(tm[r], __shfl_xor_sync(0xffffffffu, tm[r], 2));
            float mn = fmaxf(mr[r], tm[r]);
            sc[r] = __expf(mr[r] - mn);
            mr[r] = mn;
        }
        float rs[4] = {0.f, 0.f, 0.f, 0.f};
#pragma unroll
        for (int j = 0; j < 8; j++) {
            Sc0[j].x = __expf(Sc0[j].x - mr[0]);
            Sc0[j].y = __expf(Sc0[j].y - mr[0]);
            Sc0[j].z = __expf(Sc0[j].z - mr[1]);
            Sc0[j].w = __expf(Sc0[j].w - mr[1]);
            Sc1[j].x = __expf(Sc1[j].x - mr[2]);
            Sc1[j].y = __expf(Sc1[j].y - mr[2]);
            Sc1[j].z = __expf(Sc1[j].z - mr[3]);
            Sc1[j].w = __expf(Sc1[j].w - mr[3]);
            rs[0] += Sc0[j].x + Sc0[j].y;
            rs[1] += Sc0[j].z + Sc0[j].w;
            rs[2] += Sc1[j].x + Sc1[j].y;
            rs[3] += Sc1[j].z + Sc1[j].w;
        }
#pragma unroll
        for (int r = 0; r < 4; r++) {
            rs[r] += __shfl_xor_sync(0xffffffffu, rs[r], 1);
            rs[r] += __shfl_xor_sync(0xffffffffu, rs[r], 2);
            lr[r] = lr[r] * sc[r] + rs[r];
        }
#pragma unroll
        for (int j = 0; j < 8; j++) {
            Oc0[j].x *= sc[0]; Oc0[j].y *= sc[0];
            Oc0[j].z *= sc[1]; Oc0[j].w *= sc[1];
            Oc1[j].x *= sc[2]; Oc1[j].y *= sc[2];
            Oc1[j].z *= sc[3]; Oc1[j].w *= sc[3];
        }

        uint32_t Pa0[4][4], Pa1[4][4];
#pragma unroll
        for (int c = 0; c < 4; c++) {
            Pa0[c][0] = pkbf(Sc0[2*c].x,     Sc0[2*c].y);
            Pa0[c][1] = pkbf(Sc0[2*c].z,     Sc0[2*c].w);
            Pa0[c][2] = pkbf(Sc0[2*c + 1].x, Sc0[2*c + 1].y);
            Pa0[c][3] = pkbf(Sc0[2*c + 1].z, Sc0[2*c + 1].w);
            Pa1[c][0] = pkbf(Sc1[2*c].x,     Sc1[2*c].y);
            Pa1[c][1] = pkbf(Sc1[2*c].z,     Sc1[2*c].w);
            Pa1[c][2] = pkbf(Sc1[2*c + 1].x, Sc1[2*c + 1].y);
            Pa1[c][3] = pkbf(Sc1[2*c + 1].z, Sc1[2*c + 1].w);
        }

#pragma unroll
        for (int j = 0; j < 8; j++) {
            uint4 vA = Vf4[(j * 2 + 0) * 32 + lane];
            uint4 vB = Vf4[(j * 2 + 1) * 32 + lane];
            mma16(Oc0[j], Pa0[0], vA.x, vA.y);
            mma16(Oc0[j], Pa0[1], vA.z, vA.w);
            mma16(Oc0[j], Pa0[2], vB.x, vB.y);
            mma16(Oc0[j], Pa0[3], vB.z, vB.w);
            mma16(Oc1[j], Pa1[0], vA.x, vA.y);
            mma16(Oc1[j], Pa1[1], vA.z, vA.w);
            mma16(Oc1[j], Pa1[2], vB.x, vB.y);
            mma16(Oc1[j], Pa1[3], vB.z, vB.w);
        }
    }

    const float i0 = 1.f / lr[0], i1 = 1.f / lr[1];
    const float i2 = 1.f / lr[2], i3 = 1.f / lr[3];
    float* op = g_att + ((size_t)b * 2048 + qt * 128 + wid * 32) * 512 + h * 64;
#pragma unroll
    for (int j = 0; j < 8; j++) {
        int col = j * 8 + 2 * tg;
        *(float2*)(op + (size_t)g * 512 + col) =
            make_float2(Oc0[j].x * i0, Oc0[j].y * i0);
        *(float2*)(op + (size_t)(g + 8) * 512 + col) =
            make_float2(Oc0[j].z * i1, Oc0[j].w * i1);
        *(float2*)(op + (size_t)(g + 16) * 512 + col) =
            make_float2(Oc1[j].x * i2, Oc1[j].y * i2);
        *(float2*)(op + (size_t)(g + 24) * 512 + col) =
            make_float2(Oc1[j].z * i3, Oc1[j].w * i3);
    }
}

// ---------------------------------------------------------------------------
// LayerNorm in-place on d_out
// ---------------------------------------------------------------------------
__global__ __launch_bounds__(128) void ln_kernel(
    float* __restrict__ y, const float* __restrict__ g,
    const float* __restrict__ be)
{
    const int row = blockIdx.x;
    const int tid = threadIdx.x;
    float4 v = *(const float4*)(y + (size_t)row * 512 + tid * 4);
    float s = (v.x + v.y) + (v.z + v.w);
    float q = (v.x * v.x + v.y * v.y) + (v.z * v.z + v.w * v.w);
#pragma unroll
    for (int msk = 16; msk; msk >>= 1) {
        s += __shfl_xor_sync(0xffffffffu, s, msk);
        q += __shfl_xor_sync(0xffffffffu, q, msk);
    }
    __shared__ float ss[4], sq[4];
    const int w = tid >> 5;
    if ((tid & 31) == 0) { ss[w] = s; sq[w] = q; }
    __syncthreads();
    s = (ss[0] + ss[1]) + (ss[2] + ss[3]);
    q = (sq[0] + sq[1]) + (sq[2] + sq[3]);
    const float mu = s * (1.0f / 512.0f);
    const float var = q * (1.0f / 512.0f) - mu * mu;
    const float rs = rsqrtf(var + 1e-5f);
    float4 gg = *(const float4*)(g + tid * 4);
    float4 bb = *(const float4*)(be + tid * 4);
    float4 r;
    r.x = (v.x - mu) * rs * gg.x + bb.x;
    r.y = (v.y - mu) * rs * gg.y + bb.y;
    r.z = (v.z - mu) * rs * gg.z + bb.z;
    r.w = (v.w - mu) * rs * gg.w + bb.w;
    *(float4*)(y + (size_t)row * 512 + tid * 4) = r;
}

// ---------------------------------------------------------------------------
extern "C" void kernel_launch(void* const* d_in, const int* in_sizes, int n_in,
                              void* d_out, int out_size)
{
    const float* xp      = (const float*)d_in[0];
    const float* xpcre   = (const float*)d_in[1];
    const float* bias    = (const float*)d_in[2];
    const void*  mask    = d_in[3];
    const float* Wq      = (const float*)d_in[4];
    const float* Wkv     = (const float*)d_in[5];
    const float* Wff     = (const float*)d_in[6];
    const float* bff     = (const float*)d_in[7];
    const float* gamma_f = (const float*)d_in[8];
    const float* ln_g    = (const float*)d_in[9];
    const float* ln_b    = (const float*)d_in[10];
    float* out = (float*)d_out;

    const int attn_smem = 2 * ASTG * 4;     // 106496 B
    const int proj_smem = 2 * PSTG * 4;     // 40960 B
    const int gemm_smem = 2 * STG_F * 4;    // 37888 B
    cudaFuncSetAttribute(attn_mma_kernel,
                         cudaFuncAttributeMaxDynamicSharedMemorySize, attn_smem);
    cudaFuncSetAttribute(proj_bf_kernel,
                         cudaFuncAttributeMaxDynamicSharedMemorySize, proj_smem);
    cudaFuncSetAttribute(ff_tc_kernel,
                         cudaFuncAttributeMaxDynamicSharedMemorySize, gemm_smem);

    mask_norm_kernel<<<1, 256>>>(mask);
    conv_x_kernel<<<BB * SS, 256>>>(xp, xpcre);
    dim3 wg(32, 16, 2);
    conv_w_kernel<<<wg, 256>>>(Wq, Wkv);

    dim3 pg(12, 128);
    proj_bf_kernel<<<pg, 256, proj_smem>>>();

    dim3 rg(32, 64, 2);
    repack_kv_kernel<<<rg, 256>>>();

    dim3 ag(16, 8, 8);   // (qtile128, h, b), 4 warps x 32 rows
    attn_mma_kernel<<<ag, 128, attn_smem>>>(bias, gamma_f);

    dim3 fg(4, 128);
    ff_tc_kernel<<<fg, 256, gemm_smem>>>(Wff, bff, xp, out);

    ln_kernel<<<BB * SS, 128>>>(out, ln_g, ln_b);
}